// round 1
// baseline (speedup 1.0000x reference)
#include <cuda_runtime.h>
#include <math.h>

#define BSZ   8
#define LSEQ  2048
#define HDIM  512
#define NST   64
#define ROWS  (BSZ*LSEQ)      // 16384

// ---------------- scratch (device globals; no allocation allowed) ----------------
__device__ float g_wre[HDIM*NST];
__device__ float g_wim[HDIM*NST];
__device__ float g_ctre[HDIM*NST];
__device__ float g_ctim[HDIM*NST];

__device__ float g_yact[(size_t)ROWS*HDIM];   // S4 activation (post gelu), (B,L,H)
__device__ float g_z   [(size_t)ROWS*2*HDIM]; // GLU pre-activation
__device__ float g_xln [(size_t)ROWS*HDIM];   // after residual + LN1
__device__ float g_y1  [(size_t)ROWS*HDIM];   // FFN hidden
__device__ float g_y2  [(size_t)ROWS*HDIM];   // FFN out

// ---------------- precompute w = exp(dt*A), Ct = C*(exp(dt*A)-1)/A ----------------
__global__ void precompute_kernel(const float* __restrict__ log_dt,
                                  const float* __restrict__ Are,
                                  const float* __restrict__ Aim,
                                  const float* __restrict__ Cre,
                                  const float* __restrict__ Cim) {
    int h = blockIdx.x, n = threadIdx.x;
    int idx = h * NST + n;
    float dt = expf(log_dt[h]);
    float ar = Are[idx] * dt;
    float ai = Aim[idx] * dt;
    float e  = expf(ar);
    float sb, cb;
    sincosf(ai, &sb, &cb);
    float wre = e * cb, wim = e * sb;
    // E = exp(dtA) - 1 ; ratio = E / A
    float Ere = wre - 1.0f, Eim = wim;
    float Ar = Are[idx], Ai = Aim[idx];
    float inv = 1.0f / (Ar * Ar + Ai * Ai);
    float rre = (Ere * Ar + Eim * Ai) * inv;
    float rim = (Eim * Ar - Ere * Ai) * inv;
    float cr = Cre[idx], ci = Cim[idx];
    g_ctre[idx] = cr * rre - ci * rim;
    g_ctim[idx] = cr * rim + ci * rre;
    g_wre[idx]  = wre;
    g_wim[idx]  = wim;
}

// ---------------- SSM scan: 8 threads per (b,h), 8 complex states per thread ------
__device__ __forceinline__ float gelu_tanh(float v) {
    float c = 0.7978845608028654f * (v + 0.044715f * v * v * v);
    return 0.5f * v * (1.0f + tanhf(c));
}

__global__ __launch_bounds__(256) void scan_kernel(const float* __restrict__ x,
                                                   const float* __restrict__ Dskip,
                                                   float* __restrict__ yact) {
    int tid  = threadIdx.x;
    int gid  = blockIdx.x * (blockDim.x / 8) + (tid >> 3);   // group = b*HDIM + h
    int lane = tid & 7;
    int b = gid >> 9;        // / HDIM
    int h = gid & (HDIM - 1);

    float wre[8], wim[8], cre[8], cim[8], sre[8], sim[8];
    int base = h * NST + lane * 8;
#pragma unroll
    for (int j = 0; j < 8; j++) {
        wre[j] = g_wre[base + j];
        wim[j] = g_wim[base + j];
        cre[j] = g_ctre[base + j];
        cim[j] = g_ctim[base + j];
        sre[j] = 0.0f; sim[j] = 0.0f;
    }
    float Dv = Dskip[h];
    const float* xp = x + (size_t)b * LSEQ * HDIM + h;
    float* yp = yact + (size_t)b * LSEQ * HDIM + h;

    for (int l = 0; l < LSEQ; l++) {
        float u = __ldg(xp + (size_t)l * HDIM);
        float acc = 0.0f;
#pragma unroll
        for (int j = 0; j < 8; j++) {
            float nr = fmaf(wre[j], sre[j], fmaf(-wim[j], sim[j], u));
            float ni = fmaf(wim[j], sre[j], wre[j] * sim[j]);
            sre[j] = nr; sim[j] = ni;
            acc = fmaf(cre[j], nr, acc);
            acc = fmaf(-cim[j], ni, acc);
        }
        acc += __shfl_xor_sync(0xffffffffu, acc, 1);
        acc += __shfl_xor_sync(0xffffffffu, acc, 2);
        acc += __shfl_xor_sync(0xffffffffu, acc, 4);
        if (lane == 0) {
            float v = 2.0f * acc + Dv * u;
            yp[(size_t)l * HDIM] = gelu_tanh(v);
        }
    }
}

// ---------------- tiled fp32 GEMM:  C[M,N] = A[M,K] @ W[N,K]^T + bias ------------
// act: 0 = none, 1 = relu
#define BM 64
#define BN 64
#define BK 16
__global__ __launch_bounds__(256) void gemm_nt(const float* __restrict__ A,
                                               const float* __restrict__ W,
                                               const float* __restrict__ bias,
                                               float* __restrict__ C,
                                               int M, int N, int K, int act) {
    __shared__ float As[BK][BM + 4];
    __shared__ float Ws[BK][BN + 4];

    int t  = threadIdx.x;
    int tx = t & 15;          // N direction (x4)
    int ty = t >> 4;          // M direction (x4)
    int row0 = blockIdx.y * BM;
    int col0 = blockIdx.x * BN;

    int lr = t >> 2;          // 0..63  tile row
    int lc = (t & 3) * 4;     // 0,4,8,12 tile col (k)

    float acc[4][4];
#pragma unroll
    for (int i = 0; i < 4; i++)
#pragma unroll
        for (int j = 0; j < 4; j++) acc[i][j] = 0.0f;

    for (int k0 = 0; k0 < K; k0 += BK) {
        float4 av = *(const float4*)(A + (size_t)(row0 + lr) * K + k0 + lc);
        float4 wv = *(const float4*)(W + (size_t)(col0 + lr) * K + k0 + lc);
        As[lc + 0][lr] = av.x; As[lc + 1][lr] = av.y;
        As[lc + 2][lr] = av.z; As[lc + 3][lr] = av.w;
        Ws[lc + 0][lr] = wv.x; Ws[lc + 1][lr] = wv.y;
        Ws[lc + 2][lr] = wv.z; Ws[lc + 3][lr] = wv.w;
        __syncthreads();
#pragma unroll
        for (int kk = 0; kk < BK; kk++) {
            float4 a4 = *(const float4*)&As[kk][ty * 4];
            float4 b4 = *(const float4*)&Ws[kk][tx * 4];
            float a[4] = {a4.x, a4.y, a4.z, a4.w};
            float bb[4] = {b4.x, b4.y, b4.z, b4.w};
#pragma unroll
            for (int i = 0; i < 4; i++)
#pragma unroll
                for (int j = 0; j < 4; j++)
                    acc[i][j] = fmaf(a[i], bb[j], acc[i][j]);
        }
        __syncthreads();
    }

    float bv[4];
#pragma unroll
    for (int j = 0; j < 4; j++) bv[j] = bias[col0 + tx * 4 + j];
#pragma unroll
    for (int i = 0; i < 4; i++) {
        float4 o;
        float* op = (float*)&o;
#pragma unroll
        for (int j = 0; j < 4; j++) {
            float v = acc[i][j] + bv[j];
            if (act == 1) v = fmaxf(v, 0.0f);
            op[j] = v;
        }
        *(float4*)(C + (size_t)(row0 + ty * 4 + i) * N + col0 + tx * 4) = o;
    }
}

// ---------------- block reduce helper (128 threads) ------------------------------
__device__ __forceinline__ float2 block_reduce_2(float a, float b) {
    unsigned m = 0xffffffffu;
#pragma unroll
    for (int o = 16; o > 0; o >>= 1) {
        a += __shfl_down_sync(m, a, o);
        b += __shfl_down_sync(m, b, o);
    }
    __shared__ float sa[4], sb[4];
    int w = threadIdx.x >> 5, lane = threadIdx.x & 31;
    if (lane == 0) { sa[w] = a; sb[w] = b; }
    __syncthreads();
    if (threadIdx.x == 0) {
        float ta = sa[0] + sa[1] + sa[2] + sa[3];
        float tb = sb[0] + sb[1] + sb[2] + sb[3];
        sa[0] = ta; sb[0] = tb;
    }
    __syncthreads();
    return make_float2(sa[0], sb[0]);
}

// ---------------- GLU + residual + LayerNorm1 ------------------------------------
__global__ __launch_bounds__(128) void glu_ln_kernel(const float* __restrict__ z,
                                                     const float* __restrict__ x,
                                                     const float* __restrict__ g1,
                                                     const float* __restrict__ b1,
                                                     float* __restrict__ xln) {
    int row = blockIdx.x, tid = threadIdx.x;
    const float* zr = z + (size_t)row * (2 * HDIM);
    const float* xr = x + (size_t)row * HDIM;
    float v[4], s = 0.0f, s2 = 0.0f;
#pragma unroll
    for (int i = 0; i < 4; i++) {
        int c = tid + i * 128;
        float a = zr[c], g = zr[c + HDIM];
        float val = xr[c] + a / (1.0f + expf(-g));
        v[i] = val; s += val; s2 += val * val;
    }
    float2 tot = block_reduce_2(s, s2);
    float mu = tot.x * (1.0f / HDIM);
    float var = tot.y * (1.0f / HDIM) - mu * mu;
    float rstd = rsqrtf(var + 1e-5f);
#pragma unroll
    for (int i = 0; i < 4; i++) {
        int c = tid + i * 128;
        xln[(size_t)row * HDIM + c] = (v[i] - mu) * rstd * g1[c] + b1[c];
    }
}

// ---------------- residual + LayerNorm2 (final output) ---------------------------
__global__ __launch_bounds__(128) void final_ln_kernel(const float* __restrict__ xln,
                                                       const float* __restrict__ y2,
                                                       const float* __restrict__ g2,
                                                       const float* __restrict__ b2,
                                                       float* __restrict__ out) {
    int row = blockIdx.x, tid = threadIdx.x;
    const float* a = xln + (size_t)row * HDIM;
    const float* b = y2 + (size_t)row * HDIM;
    float v[4], s = 0.0f, s2 = 0.0f;
#pragma unroll
    for (int i = 0; i < 4; i++) {
        int c = tid + i * 128;
        float val = a[c] + b[c];
        v[i] = val; s += val; s2 += val * val;
    }
    float2 tot = block_reduce_2(s, s2);
    float mu = tot.x * (1.0f / HDIM);
    float var = tot.y * (1.0f / HDIM) - mu * mu;
    float rstd = rsqrtf(var + 1e-5f);
#pragma unroll
    for (int i = 0; i < 4; i++) {
        int c = tid + i * 128;
        out[(size_t)row * HDIM + c] = (v[i] - mu) * rstd * g2[c] + b2[c];
    }
}

// ---------------- launch ----------------------------------------------------------
extern "C" void kernel_launch(void* const* d_in, const int* in_sizes, int n_in,
                              void* d_out, int out_size) {
    const float* x      = (const float*)d_in[0];
    const float* log_dt = (const float*)d_in[1];
    const float* A_re   = (const float*)d_in[2];
    const float* A_im   = (const float*)d_in[3];
    const float* C_re   = (const float*)d_in[4];
    const float* C_im   = (const float*)d_in[5];
    const float* D_skip = (const float*)d_in[6];
    const float* W_out  = (const float*)d_in[7];
    const float* b_out  = (const float*)d_in[8];
    const float* g1     = (const float*)d_in[9];
    const float* beta1  = (const float*)d_in[10];
    const float* g2     = (const float*)d_in[11];
    const float* beta2  = (const float*)d_in[12];
    const float* W1     = (const float*)d_in[13];
    const float* bc1    = (const float*)d_in[14];
    const float* W2     = (const float*)d_in[15];
    const float* bc2    = (const float*)d_in[16];
    float* out = (float*)d_out;

    float *yact, *z, *xln, *y1, *y2;
    cudaGetSymbolAddress((void**)&yact, g_yact);
    cudaGetSymbolAddress((void**)&z,    g_z);
    cudaGetSymbolAddress((void**)&xln,  g_xln);
    cudaGetSymbolAddress((void**)&y1,   g_y1);
    cudaGetSymbolAddress((void**)&y2,   g_y2);

    // 1) discretize SSM params
    precompute_kernel<<<HDIM, NST>>>(log_dt, A_re, A_im, C_re, C_im);

    // 2) SSM recurrence + D skip + gelu -> yact (B,L,H)
    scan_kernel<<<(BSZ * HDIM * 8) / 256, 256>>>(x, D_skip, yact);

    // 3) output projection (GLU pre-act): z = yact @ W_out^T + b_out
    gemm_nt<<<dim3((2 * HDIM) / BN, ROWS / BM), 256>>>(yact, W_out, b_out, z,
                                                       ROWS, 2 * HDIM, HDIM, 0);

    // 4) GLU + residual + LN1 -> xln
    glu_ln_kernel<<<ROWS, 128>>>(z, x, g1, beta1, xln);

    // 5) FFN: y1 = relu(xln @ W1^T + bc1)
    gemm_nt<<<dim3(HDIM / BN, ROWS / BM), 256>>>(xln, W1, bc1, y1,
                                                 ROWS, HDIM, HDIM, 1);

    // 6) y2 = y1 @ W2^T + bc2
    gemm_nt<<<dim3(HDIM / BN, ROWS / BM), 256>>>(y1, W2, bc2, y2,
                                                 ROWS, HDIM, HDIM, 0);

    // 7) out = LN2(xln + y2)
    final_ln_kernel<<<ROWS, 128>>>(xln, y2, g2, beta2, out);
}

// round 3
// speedup vs baseline: 1.3282x; 1.3282x over previous
#include <cuda_runtime.h>
#include <cuda_bf16.h>
#include <math.h>
#include <stdint.h>

#define BSZ   8
#define LSEQ  2048
#define HDIM  512
#define NST   64
#define ROWS  (BSZ*LSEQ)      // 16384

// ---------------- scratch (device globals; no allocation allowed) ----------------
__device__ float g_wre[HDIM*NST];
__device__ float g_wim[HDIM*NST];
__device__ float g_ctre[HDIM*NST];
__device__ float g_ctim[HDIM*NST];

__device__ float g_yact[(size_t)ROWS*HDIM];   // S4 activation (post gelu), (B,L,H)
__device__ float g_z   [(size_t)ROWS*2*HDIM]; // GLU pre-activation
__device__ float g_xln [(size_t)ROWS*HDIM];   // after residual + LN1
__device__ float g_y1  [(size_t)ROWS*HDIM];   // FFN hidden
__device__ float g_y2  [(size_t)ROWS*HDIM];   // FFN out

// =============================== helpers =========================================
__device__ __forceinline__ uint32_t smem_u32(const void* p) {
    uint32_t a;
    asm("{ .reg .u64 t; cvta.to.shared.u64 t, %1; cvt.u32.u64 %0, t; }" : "=r"(a) : "l"(p));
    return a;
}

__device__ __forceinline__ void ldmatrix_x4(uint32_t* r, uint32_t addr) {
    asm volatile("ldmatrix.sync.aligned.m8n8.x4.shared.b16 {%0,%1,%2,%3}, [%4];"
        : "=r"(r[0]), "=r"(r[1]), "=r"(r[2]), "=r"(r[3]) : "r"(addr));
}

__device__ __forceinline__ void mma_bf16(float* c, const uint32_t* a,
                                         uint32_t b0, uint32_t b1) {
    asm volatile("mma.sync.aligned.m16n8k16.row.col.f32.bf16.bf16.f32 "
        "{%0,%1,%2,%3}, {%4,%5,%6,%7}, {%8,%9}, {%0,%1,%2,%3};"
        : "+f"(c[0]), "+f"(c[1]), "+f"(c[2]), "+f"(c[3])
        : "r"(a[0]), "r"(a[1]), "r"(a[2]), "r"(a[3]), "r"(b0), "r"(b1));
}

// split fp32x4 -> hi bf16x2 pair + lo bf16x2 pair
__device__ __forceinline__ void split4(float4 v, uint32_t* hi, uint32_t* lo) {
    __nv_bfloat162 h01 = __float22bfloat162_rn(make_float2(v.x, v.y));
    __nv_bfloat162 h23 = __float22bfloat162_rn(make_float2(v.z, v.w));
    float2 f01 = __bfloat1622float2(h01);
    float2 f23 = __bfloat1622float2(h23);
    __nv_bfloat162 l01 = __float22bfloat162_rn(make_float2(v.x - f01.x, v.y - f01.y));
    __nv_bfloat162 l23 = __float22bfloat162_rn(make_float2(v.z - f23.x, v.w - f23.y));
    hi[0] = *(uint32_t*)&h01; hi[1] = *(uint32_t*)&h23;
    lo[0] = *(uint32_t*)&l01; lo[1] = *(uint32_t*)&l23;
}

#define STS128(addr, r0, r1, r2, r3) \
    asm volatile("st.shared.v4.b32 [%0], {%1,%2,%3,%4};" \
                 :: "r"(addr), "r"(r0), "r"(r1), "r"(r2), "r"(r3) : "memory")

// ---------------- precompute w = exp(dt*A), Ct = C*(exp(dt*A)-1)/A ----------------
__global__ void precompute_kernel(const float* __restrict__ log_dt,
                                  const float* __restrict__ Are,
                                  const float* __restrict__ Aim,
                                  const float* __restrict__ Cre,
                                  const float* __restrict__ Cim) {
    int h = blockIdx.x, n = threadIdx.x;
    int idx = h * NST + n;
    float dt = expf(log_dt[h]);
    float ar = Are[idx] * dt;
    float ai = Aim[idx] * dt;
    float e  = expf(ar);
    float sb, cb;
    sincosf(ai, &sb, &cb);
    float wre = e * cb, wim = e * sb;
    float Ere = wre - 1.0f, Eim = wim;
    float Ar = Are[idx], Ai = Aim[idx];
    float inv = 1.0f / (Ar * Ar + Ai * Ai);
    float rre = (Ere * Ar + Eim * Ai) * inv;
    float rim = (Eim * Ar - Ere * Ai) * inv;
    float cr = Cre[idx], ci = Cim[idx];
    g_ctre[idx] = cr * rre - ci * rim;
    g_ctim[idx] = cr * rim + ci * rre;
    g_wre[idx]  = wre;
    g_wim[idx]  = wim;
}

// ---------------- SSM scan: 8 threads per (b,h), 8 complex states per thread ------
__device__ __forceinline__ float gelu_tanh(float v) {
    float c = 0.7978845608028654f * (v + 0.044715f * v * v * v);
    return 0.5f * v * (1.0f + tanhf(c));
}

__global__ __launch_bounds__(256) void scan_kernel(const float* __restrict__ x,
                                                   const float* __restrict__ Dskip,
                                                   float* __restrict__ yact) {
    int tid  = threadIdx.x;
    int gid  = blockIdx.x * (blockDim.x / 8) + (tid >> 3);
    int lane = tid & 7;
    int b = gid >> 9;
    int h = gid & (HDIM - 1);

    float wre[8], wim[8], cre[8], cim[8], sre[8], sim[8];
    int base = h * NST + lane * 8;
#pragma unroll
    for (int j = 0; j < 8; j++) {
        wre[j] = g_wre[base + j];
        wim[j] = g_wim[base + j];
        cre[j] = g_ctre[base + j];
        cim[j] = g_ctim[base + j];
        sre[j] = 0.0f; sim[j] = 0.0f;
    }
    float Dv = Dskip[h];
    const float* xp = x + (size_t)b * LSEQ * HDIM + h;
    float* yp = yact + (size_t)b * LSEQ * HDIM + h;

    for (int l = 0; l < LSEQ; l++) {
        float u = __ldg(xp + (size_t)l * HDIM);
        float acc = 0.0f;
#pragma unroll
        for (int j = 0; j < 8; j++) {
            float nr = fmaf(wre[j], sre[j], fmaf(-wim[j], sim[j], u));
            float ni = fmaf(wim[j], sre[j], wre[j] * sim[j]);
            sre[j] = nr; sim[j] = ni;
            acc = fmaf(cre[j], nr, acc);
            acc = fmaf(-cim[j], ni, acc);
        }
        acc += __shfl_xor_sync(0xffffffffu, acc, 1);
        acc += __shfl_xor_sync(0xffffffffu, acc, 2);
        acc += __shfl_xor_sync(0xffffffffu, acc, 4);
        if (lane == 0) {
            float v = 2.0f * acc + Dv * u;
            yp[(size_t)l * HDIM] = gelu_tanh(v);
        }
    }
}

// ======================= mma.sync split-bf16 GEMM =================================
// C[M,N] = A[M,K] @ W[N,K]^T + bias ; fp32 in/out, 3-term bf16 split, fp32 accum.
// Block 256 thr (8 warps, 4x2 warp grid), tile 128x128, K-chunk 32, double buffer.
#define LDSB  80                    // bytes per smem tile row (32 bf16 + 8 pad)
#define TILEB (128 * LDSB)          // 10240 bytes per tile
#define STAGEB (4 * TILEB)          // Ah, Al, Bh, Bl
#define GEMM_SMEM (2 * STAGEB)      // 81920 bytes

__global__ void __launch_bounds__(256, 1)
gemm_mma(const float* __restrict__ A, const float* __restrict__ W,
         const float* __restrict__ bias, float* __restrict__ C,
         int K, int N, int act) {
    extern __shared__ char smem[];
    uint32_t sbase = smem_u32(smem);
    int tid = threadIdx.x, wid = tid >> 5, lane = tid & 31;
    int row0 = blockIdx.y * 128, col0 = blockIdx.x * 128;
    int wm = wid >> 1, wn = wid & 1;

    float acc[2][8][4];
#pragma unroll
    for (int i = 0; i < 2; i++)
#pragma unroll
        for (int j = 0; j < 8; j++)
#pragma unroll
            for (int q = 0; q < 4; q++) acc[i][j][q] = 0.0f;

    // gmem load mapping: 2 threads per row, each 16 consecutive floats
    int lr = tid >> 1;
    int lc = (tid & 1) * 16;
    const float* ap = A + (size_t)(row0 + lr) * K + lc;
    const float* bp = W + (size_t)(col0 + lr) * K + lc;
    uint32_t soff = (uint32_t)(lr * LDSB + lc * 2);

    float4 ra[4], rb[4];
#pragma unroll
    for (int i = 0; i < 4; i++) {
        ra[i] = *(const float4*)(ap + i * 4);
        rb[i] = *(const float4*)(bp + i * 4);
    }

    int nch = K / 32;
    for (int c = 0; c < nch; ++c) {
        int buf = c & 1;
        uint32_t ah = sbase + buf * STAGEB;
        uint32_t al = ah + TILEB;
        uint32_t bh = al + TILEB;
        uint32_t bl = bh + TILEB;

        // convert + store this chunk
        {
            uint32_t hi[4], lo[4];
            split4(ra[0], hi, lo); split4(ra[1], hi + 2, lo + 2);
            STS128(ah + soff, hi[0], hi[1], hi[2], hi[3]);
            STS128(al + soff, lo[0], lo[1], lo[2], lo[3]);
            split4(ra[2], hi, lo); split4(ra[3], hi + 2, lo + 2);
            STS128(ah + soff + 16, hi[0], hi[1], hi[2], hi[3]);
            STS128(al + soff + 16, lo[0], lo[1], lo[2], lo[3]);

            split4(rb[0], hi, lo); split4(rb[1], hi + 2, lo + 2);
            STS128(bh + soff, hi[0], hi[1], hi[2], hi[3]);
            STS128(bl + soff, lo[0], lo[1], lo[2], lo[3]);
            split4(rb[2], hi, lo); split4(rb[3], hi + 2, lo + 2);
            STS128(bh + soff + 16, hi[0], hi[1], hi[2], hi[3]);
            STS128(bl + soff + 16, lo[0], lo[1], lo[2], lo[3]);
        }
        __syncthreads();

        // prefetch next chunk (overlaps with MMA below)
        if (c + 1 < nch) {
            const float* ap2 = ap + (c + 1) * 32;
            const float* bp2 = bp + (c + 1) * 32;
#pragma unroll
            for (int i = 0; i < 4; i++) {
                ra[i] = *(const float4*)(ap2 + i * 4);
                rb[i] = *(const float4*)(bp2 + i * 4);
            }
        }

        // compute: 2 k16 steps
        int r_lm = (lane & 7) + ((lane >> 3) & 1) * 8;  // row-within-16 for ldmatrix
        int k_lm = ((lane >> 4) & 1) * 8;               // k-col-within-16
#pragma unroll
        for (int ks = 0; ks < 2; ++ks) {
            uint32_t afh[2][4], afl[2][4], bfh[4][4], bfl[4][4];
            int kcol = ks * 16 + k_lm;
#pragma unroll
            for (int mi = 0; mi < 2; ++mi) {
                int m = wm * 32 + mi * 16 + r_lm;
                uint32_t ad = ah + (uint32_t)(m * LDSB + kcol * 2);
                ldmatrix_x4(afh[mi], ad);
                ldmatrix_x4(afl[mi], ad + TILEB);
            }
#pragma unroll
            for (int nj = 0; nj < 4; ++nj) {
                int n = wn * 64 + nj * 16 + r_lm;
                uint32_t bd = bh + (uint32_t)(n * LDSB + kcol * 2);
                ldmatrix_x4(bfh[nj], bd);
                ldmatrix_x4(bfl[nj], bd + TILEB);
            }
#pragma unroll
            for (int mi = 0; mi < 2; ++mi)
#pragma unroll
                for (int nj = 0; nj < 4; ++nj)
#pragma unroll
                    for (int h = 0; h < 2; ++h) {
                        float* cc = acc[mi][nj * 2 + h];
                        mma_bf16(cc, afh[mi], bfh[nj][h], bfh[nj][2 + h]);
                        mma_bf16(cc, afh[mi], bfl[nj][h], bfl[nj][2 + h]);
                        mma_bf16(cc, afl[mi], bfh[nj][h], bfh[nj][2 + h]);
                    }
        }
    }

    // epilogue
    int tg = lane >> 2, tq = lane & 3;
#pragma unroll
    for (int mi = 0; mi < 2; ++mi) {
        int r = row0 + wm * 32 + mi * 16 + tg;
#pragma unroll
        for (int ni = 0; ni < 8; ++ni) {
            int cix = col0 + wn * 64 + ni * 8 + tq * 2;
            float b0 = bias[cix], b1 = bias[cix + 1];
            float v0 = acc[mi][ni][0] + b0, v1 = acc[mi][ni][1] + b1;
            float v2 = acc[mi][ni][2] + b0, v3 = acc[mi][ni][3] + b1;
            if (act == 1) {
                v0 = fmaxf(v0, 0.0f); v1 = fmaxf(v1, 0.0f);
                v2 = fmaxf(v2, 0.0f); v3 = fmaxf(v3, 0.0f);
            }
            *(float2*)(C + (size_t)r * N + cix) = make_float2(v0, v1);
            *(float2*)(C + (size_t)(r + 8) * N + cix) = make_float2(v2, v3);
        }
    }
}

// ---------------- block reduce helper (128 threads) ------------------------------
__device__ __forceinline__ float2 block_reduce_2(float a, float b) {
    unsigned m = 0xffffffffu;
#pragma unroll
    for (int o = 16; o > 0; o >>= 1) {
        a += __shfl_down_sync(m, a, o);
        b += __shfl_down_sync(m, b, o);
    }
    __shared__ float sa[4], sb[4];
    int w = threadIdx.x >> 5, lane = threadIdx.x & 31;
    if (lane == 0) { sa[w] = a; sb[w] = b; }
    __syncthreads();
    if (threadIdx.x == 0) {
        float ta = sa[0] + sa[1] + sa[2] + sa[3];
        float tb = sb[0] + sb[1] + sb[2] + sb[3];
        sa[0] = ta; sb[0] = tb;
    }
    __syncthreads();
    return make_float2(sa[0], sb[0]);
}

// ---------------- GLU + residual + LayerNorm1 ------------------------------------
__global__ __launch_bounds__(128) void glu_ln_kernel(const float* __restrict__ z,
                                                     const float* __restrict__ x,
                                                     const float* __restrict__ g1,
                                                     const float* __restrict__ b1,
                                                     float* __restrict__ xln) {
    int row = blockIdx.x, tid = threadIdx.x;
    const float* zr = z + (size_t)row * (2 * HDIM);
    const float* xr = x + (size_t)row * HDIM;
    float v[4], s = 0.0f, s2 = 0.0f;
#pragma unroll
    for (int i = 0; i < 4; i++) {
        int c = tid + i * 128;
        float a = zr[c], g = zr[c + HDIM];
        float val = xr[c] + a / (1.0f + expf(-g));
        v[i] = val; s += val; s2 += val * val;
    }
    float2 tot = block_reduce_2(s, s2);
    float mu = tot.x * (1.0f / HDIM);
    float var = tot.y * (1.0f / HDIM) - mu * mu;
    float rstd = rsqrtf(var + 1e-5f);
#pragma unroll
    for (int i = 0; i < 4; i++) {
        int c = tid + i * 128;
        xln[(size_t)row * HDIM + c] = (v[i] - mu) * rstd * g1[c] + b1[c];
    }
}

// ---------------- residual + LayerNorm2 (final output) ---------------------------
__global__ __launch_bounds__(128) void final_ln_kernel(const float* __restrict__ xln,
                                                       const float* __restrict__ y2,
                                                       const float* __restrict__ g2,
                                                       const float* __restrict__ b2,
                                                       float* __restrict__ out) {
    int row = blockIdx.x, tid = threadIdx.x;
    const float* a = xln + (size_t)row * HDIM;
    const float* b = y2 + (size_t)row * HDIM;
    float v[4], s = 0.0f, s2 = 0.0f;
#pragma unroll
    for (int i = 0; i < 4; i++) {
        int c = tid + i * 128;
        float val = a[c] + b[c];
        v[i] = val; s += val; s2 += val * val;
    }
    float2 tot = block_reduce_2(s, s2);
    float mu = tot.x * (1.0f / HDIM);
    float var = tot.y * (1.0f / HDIM) - mu * mu;
    float rstd = rsqrtf(var + 1e-5f);
#pragma unroll
    for (int i = 0; i < 4; i++) {
        int c = tid + i * 128;
        out[(size_t)row * HDIM + c] = (v[i] - mu) * rstd * g2[c] + b2[c];
    }
}

// ---------------- launch ----------------------------------------------------------
extern "C" void kernel_launch(void* const* d_in, const int* in_sizes, int n_in,
                              void* d_out, int out_size) {
    const float* x      = (const float*)d_in[0];
    const float* log_dt = (const float*)d_in[1];
    const float* A_re   = (const float*)d_in[2];
    const float* A_im   = (const float*)d_in[3];
    const float* C_re   = (const float*)d_in[4];
    const float* C_im   = (const float*)d_in[5];
    const float* D_skip = (const float*)d_in[6];
    const float* W_out  = (const float*)d_in[7];
    const float* b_out  = (const float*)d_in[8];
    const float* g1     = (const float*)d_in[9];
    const float* beta1  = (const float*)d_in[10];
    const float* g2     = (const float*)d_in[11];
    const float* beta2  = (const float*)d_in[12];
    const float* W1     = (const float*)d_in[13];
    const float* bc1    = (const float*)d_in[14];
    const float* W2     = (const float*)d_in[15];
    const float* bc2    = (const float*)d_in[16];
    float* out = (float*)d_out;

    float *yact, *z, *xln, *y1, *y2;
    cudaGetSymbolAddress((void**)&yact, g_yact);
    cudaGetSymbolAddress((void**)&z,    g_z);
    cudaGetSymbolAddress((void**)&xln,  g_xln);
    cudaGetSymbolAddress((void**)&y1,   g_y1);
    cudaGetSymbolAddress((void**)&y2,   g_y2);

    cudaFuncSetAttribute(gemm_mma, cudaFuncAttributeMaxDynamicSharedMemorySize, GEMM_SMEM);

    // 1) discretize SSM params
    precompute_kernel<<<HDIM, NST>>>(log_dt, A_re, A_im, C_re, C_im);

    // 2) SSM recurrence + D skip + gelu -> yact (B,L,H)
    scan_kernel<<<(BSZ * HDIM * 8) / 256, 256>>>(x, D_skip, yact);

    // 3) GLU projection: z = yact @ W_out^T + b_out   (tensor cores)
    gemm_mma<<<dim3((2 * HDIM) / 128, ROWS / 128), 256, GEMM_SMEM>>>(
        yact, W_out, b_out, z, HDIM, 2 * HDIM, 0);

    // 4) GLU + residual + LN1 -> xln
    glu_ln_kernel<<<ROWS, 128>>>(z, x, g1, beta1, xln);

    // 5) FFN: y1 = relu(xln @ W1^T + bc1)
    gemm_mma<<<dim3(HDIM / 128, ROWS / 128), 256, GEMM_SMEM>>>(
        xln, W1, bc1, y1, HDIM, HDIM, 1);

    // 6) y2 = y1 @ W2^T + bc2
    gemm_mma<<<dim3(HDIM / 128, ROWS / 128), 256, GEMM_SMEM>>>(
        y1, W2, bc2, y2, HDIM, HDIM, 0);

    // 7) out = LN2(xln + y2)
    final_ln_kernel<<<ROWS, 128>>>(xln, y2, g2, beta2, out);
}

// round 4
// speedup vs baseline: 2.1090x; 1.5879x over previous
#include <cuda_runtime.h>
#include <cuda_bf16.h>
#include <math.h>
#include <stdint.h>

#define BSZ   8
#define LSEQ  2048
#define HDIM  512
#define NST   64
#define ROWS  (BSZ*LSEQ)      // 16384

typedef __nv_bfloat16 bf16;
typedef __nv_bfloat162 bf162;

// ---------------- scratch (device globals; no allocation allowed) ----------------
__device__ float g_wre[HDIM*NST];
__device__ float g_wim[HDIM*NST];
__device__ float g_ctre[HDIM*NST];
__device__ float g_ctim[HDIM*NST];

__device__ bf16  g_yh [(size_t)ROWS*HDIM];    // S4 activation hi (bf16 split)
__device__ bf16  g_yl [(size_t)ROWS*HDIM];    // S4 activation lo
__device__ float g_z  [(size_t)ROWS*2*HDIM];  // GLU pre-activation (fp32)
__device__ float g_xln[(size_t)ROWS*HDIM];    // after residual + LN1 (fp32)
__device__ bf16  g_xh [(size_t)ROWS*HDIM];    // xln hi
__device__ bf16  g_xl [(size_t)ROWS*HDIM];    // xln lo
__device__ bf16  g_y1h[(size_t)ROWS*HDIM];    // FFN hidden hi
__device__ bf16  g_y1l[(size_t)ROWS*HDIM];    // FFN hidden lo
__device__ float g_y2 [(size_t)ROWS*HDIM];    // FFN out (fp32)

__device__ bf16 g_wouth[2*HDIM*HDIM];
__device__ bf16 g_woutl[2*HDIM*HDIM];
__device__ bf16 g_w1h[HDIM*HDIM];
__device__ bf16 g_w1l[HDIM*HDIM];
__device__ bf16 g_w2h[HDIM*HDIM];
__device__ bf16 g_w2l[HDIM*HDIM];

// =============================== helpers =========================================
__device__ __forceinline__ uint32_t smem_u32(const void* p) {
    uint32_t a;
    asm("{ .reg .u64 t; cvta.to.shared.u64 t, %1; cvt.u32.u64 %0, t; }" : "=r"(a) : "l"(p));
    return a;
}

__device__ __forceinline__ void ldmatrix_x4(uint32_t* r, uint32_t addr) {
    asm volatile("ldmatrix.sync.aligned.m8n8.x4.shared.b16 {%0,%1,%2,%3}, [%4];"
        : "=r"(r[0]), "=r"(r[1]), "=r"(r[2]), "=r"(r[3]) : "r"(addr));
}

__device__ __forceinline__ void mma_bf16(float* c, const uint32_t* a,
                                         uint32_t b0, uint32_t b1) {
    asm volatile("mma.sync.aligned.m16n8k16.row.col.f32.bf16.bf16.f32 "
        "{%0,%1,%2,%3}, {%4,%5,%6,%7}, {%8,%9}, {%0,%1,%2,%3};"
        : "+f"(c[0]), "+f"(c[1]), "+f"(c[2]), "+f"(c[3])
        : "r"(a[0]), "r"(a[1]), "r"(a[2]), "r"(a[3]), "r"(b0), "r"(b1));
}

#define STS128(addr, v) \
    asm volatile("st.shared.v4.b32 [%0], {%1,%2,%3,%4};" \
                 :: "r"(addr), "r"((v).x), "r"((v).y), "r"((v).z), "r"((v).w) : "memory")

__device__ __forceinline__ void split1(float v, bf16& h, bf16& l) {
    h = __float2bfloat16(v);
    l = __float2bfloat16(v - __bfloat162float(h));
}

// ---------------- weight split: fp32 -> bf16 hi/lo --------------------------------
__global__ void split_kernel(const float* __restrict__ src, bf16* __restrict__ hi,
                             bf16* __restrict__ lo, int n) {
    int i = blockIdx.x * blockDim.x + threadIdx.x;
    if (i < n) {
        float v = src[i];
        bf16 h, l; split1(v, h, l);
        hi[i] = h; lo[i] = l;
    }
}

// ---------------- precompute w = exp(dt*A), Ct = C*(exp(dt*A)-1)/A ----------------
__global__ void precompute_kernel(const float* __restrict__ log_dt,
                                  const float* __restrict__ Are,
                                  const float* __restrict__ Aim,
                                  const float* __restrict__ Cre,
                                  const float* __restrict__ Cim) {
    int h = blockIdx.x, n = threadIdx.x;
    int idx = h * NST + n;
    float dt = expf(log_dt[h]);
    float ar = Are[idx] * dt;
    float ai = Aim[idx] * dt;
    float e  = expf(ar);
    float sb, cb;
    sincosf(ai, &sb, &cb);
    float wre = e * cb, wim = e * sb;
    float Ere = wre - 1.0f, Eim = wim;
    float Ar = Are[idx], Ai = Aim[idx];
    float inv = 1.0f / (Ar * Ar + Ai * Ai);
    float rre = (Ere * Ar + Eim * Ai) * inv;
    float rim = (Eim * Ar - Ere * Ai) * inv;
    float cr = Cre[idx], ci = Cim[idx];
    g_ctre[idx] = cr * rre - ci * rim;
    g_ctim[idx] = cr * rim + ci * rre;
    g_wre[idx]  = wre;
    g_wim[idx]  = wim;
}

// ---------------- SSM scan: 8 threads per (b,h), 8 complex states per thread ------
// outputs bf16 hi/lo split of gelu(y) directly
#define PF 8
__global__ __launch_bounds__(256) void scan_kernel(const float* __restrict__ x,
                                                   const float* __restrict__ Dskip,
                                                   bf16* __restrict__ yh,
                                                   bf16* __restrict__ yl) {
    int tid  = threadIdx.x;
    int gid  = blockIdx.x * (blockDim.x / 8) + (tid >> 3);
    int lane = tid & 7;
    int b = gid >> 9;
    int h = gid & (HDIM - 1);

    float wre[8], wim[8], cre[8], cim[8], sre[8], sim[8];
    int base = h * NST + lane * 8;
#pragma unroll
    for (int j = 0; j < 8; j++) {
        wre[j] = g_wre[base + j];
        wim[j] = g_wim[base + j];
        cre[j] = g_ctre[base + j];
        cim[j] = g_ctim[base + j];
        sre[j] = 0.0f; sim[j] = 0.0f;
    }
    float Dv = Dskip[h];
    const float* xp = x + (size_t)b * LSEQ * HDIM + h;
    size_t orow = (size_t)b * LSEQ * HDIM + h;

    // prefetch ring (depth PF) to break DRAM-latency serialization
    float ubuf[PF];
#pragma unroll
    for (int i = 0; i < PF; i++) ubuf[i] = __ldg(xp + (size_t)i * HDIM);

#pragma unroll 8
    for (int l = 0; l < LSEQ; l++) {
        float u = ubuf[l & (PF - 1)];
        if (l + PF < LSEQ) ubuf[l & (PF - 1)] = __ldg(xp + (size_t)(l + PF) * HDIM);
        float acc = 0.0f;
#pragma unroll
        for (int j = 0; j < 8; j++) {
            float nr = fmaf(wre[j], sre[j], fmaf(-wim[j], sim[j], u));
            float ni = fmaf(wim[j], sre[j], wre[j] * sim[j]);
            sre[j] = nr; sim[j] = ni;
            acc = fmaf(cre[j], nr, acc);
            acc = fmaf(-cim[j], ni, acc);
        }
        acc += __shfl_xor_sync(0xffffffffu, acc, 1);
        acc += __shfl_xor_sync(0xffffffffu, acc, 2);
        acc += __shfl_xor_sync(0xffffffffu, acc, 4);
        if (lane == 0) {
            float v = 2.0f * acc + Dv * u;
            // tanh-approx gelu via sigmoid: gelu = v * sigmoid(2*c)
            float c = 0.7978845608028654f * (v + 0.044715f * v * v * v);
            float gv = v / (1.0f + __expf(-2.0f * c));
            bf16 hh, ll; split1(gv, hh, ll);
            yh[orow + (size_t)l * HDIM] = hh;
            yl[orow + (size_t)l * HDIM] = ll;
        }
    }
}

// ======================= mma.sync split-bf16 GEMM (pre-split inputs) ==============
// C[M,N] = (Ah+Al)[M,K] @ (Bh+Bl)[N,K]^T + bias ; 3-term bf16 split, fp32 accum.
// Block 256 thr (8 warps, 4x2 warp grid), tile 128x128, K-chunk 32, double buffer.
#define LDSB  80                    // bytes per smem tile row (32 bf16 + 8 pad)
#define TILEB (128 * LDSB)          // 10240 bytes per tile
#define STAGEB (4 * TILEB)          // Ah, Al, Bh, Bl
#define GEMM_SMEM (2 * STAGEB)      // 81920 bytes

__global__ void __launch_bounds__(256, 1)
gemm_mma(const bf16* __restrict__ Ah, const bf16* __restrict__ Al,
         const bf16* __restrict__ Bh, const bf16* __restrict__ Bl,
         const float* __restrict__ bias,
         float* __restrict__ C, bf16* __restrict__ Ch, bf16* __restrict__ Cl,
         int K, int N, int mode) {     // mode 0: fp32 out; 1: relu + split bf16 out
    extern __shared__ char smem[];
    uint32_t sbase = smem_u32(smem);
    int tid = threadIdx.x, wid = tid >> 5, lane = tid & 31;
    int row0 = blockIdx.y * 128, col0 = blockIdx.x * 128;
    int wm = wid >> 1, wn = wid & 1;

    float acc[2][8][4];
#pragma unroll
    for (int i = 0; i < 2; i++)
#pragma unroll
        for (int j = 0; j < 8; j++)
#pragma unroll
            for (int q = 0; q < 4; q++) acc[i][j][q] = 0.0f;

    // gmem load mapping: 2 threads per row, each 16 consecutive bf16 (32B)
    int lr = tid >> 1;
    int lc = (tid & 1) * 16;
    const bf16* aph = Ah + (size_t)(row0 + lr) * K + lc;
    const bf16* apl = Al + (size_t)(row0 + lr) * K + lc;
    const bf16* bph = Bh + (size_t)(col0 + lr) * K + lc;
    const bf16* bpl = Bl + (size_t)(col0 + lr) * K + lc;
    uint32_t soff = (uint32_t)(lr * LDSB + lc * 2);

    uint4 rah[2], ral[2], rbh[2], rbl[2];
#pragma unroll
    for (int i = 0; i < 2; i++) {
        rah[i] = *(const uint4*)(aph + i * 8);
        ral[i] = *(const uint4*)(apl + i * 8);
        rbh[i] = *(const uint4*)(bph + i * 8);
        rbl[i] = *(const uint4*)(bpl + i * 8);
    }

    int nch = K / 32;
    for (int c = 0; c < nch; ++c) {
        int buf = c & 1;
        uint32_t ah = sbase + buf * STAGEB;
        uint32_t al = ah + TILEB;
        uint32_t bh = al + TILEB;
        uint32_t bl = bh + TILEB;

        STS128(ah + soff, rah[0]); STS128(ah + soff + 16, rah[1]);
        STS128(al + soff, ral[0]); STS128(al + soff + 16, ral[1]);
        STS128(bh + soff, rbh[0]); STS128(bh + soff + 16, rbh[1]);
        STS128(bl + soff, rbl[0]); STS128(bl + soff + 16, rbl[1]);
        __syncthreads();

        // prefetch next chunk (overlaps with MMA below)
        if (c + 1 < nch) {
            int off = (c + 1) * 32;
#pragma unroll
            for (int i = 0; i < 2; i++) {
                rah[i] = *(const uint4*)(aph + off + i * 8);
                ral[i] = *(const uint4*)(apl + off + i * 8);
                rbh[i] = *(const uint4*)(bph + off + i * 8);
                rbl[i] = *(const uint4*)(bpl + off + i * 8);
            }
        }

        // compute: 2 k16 steps
        int r_lm = (lane & 7) + ((lane >> 3) & 1) * 8;
        int k_lm = ((lane >> 4) & 1) * 8;
#pragma unroll
        for (int ks = 0; ks < 2; ++ks) {
            uint32_t afh[2][4], afl[2][4], bfh[4][4], bfl[4][4];
            int kcol = ks * 16 + k_lm;
#pragma unroll
            for (int mi = 0; mi < 2; ++mi) {
                int m = wm * 32 + mi * 16 + r_lm;
                uint32_t ad = ah + (uint32_t)(m * LDSB + kcol * 2);
                ldmatrix_x4(afh[mi], ad);
                ldmatrix_x4(afl[mi], ad + TILEB);
            }
#pragma unroll
            for (int nj = 0; nj < 4; ++nj) {
                int n = wn * 64 + nj * 16 + r_lm;
                uint32_t bd = bh + (uint32_t)(n * LDSB + kcol * 2);
                ldmatrix_x4(bfh[nj], bd);
                ldmatrix_x4(bfl[nj], bd + TILEB);
            }
#pragma unroll
            for (int mi = 0; mi < 2; ++mi)
#pragma unroll
                for (int nj = 0; nj < 4; ++nj)
#pragma unroll
                    for (int h = 0; h < 2; ++h) {
                        float* cc = acc[mi][nj * 2 + h];
                        mma_bf16(cc, afh[mi], bfh[nj][h], bfh[nj][2 + h]);
                        mma_bf16(cc, afh[mi], bfl[nj][h], bfl[nj][2 + h]);
                        mma_bf16(cc, afl[mi], bfh[nj][h], bfh[nj][2 + h]);
                    }
        }
    }

    // epilogue
    int tg = lane >> 2, tq = lane & 3;
#pragma unroll
    for (int mi = 0; mi < 2; ++mi) {
        int r = row0 + wm * 32 + mi * 16 + tg;
#pragma unroll
        for (int ni = 0; ni < 8; ++ni) {
            int cix = col0 + wn * 64 + ni * 8 + tq * 2;
            float b0 = bias[cix], b1 = bias[cix + 1];
            float v0 = acc[mi][ni][0] + b0, v1 = acc[mi][ni][1] + b1;
            float v2 = acc[mi][ni][2] + b0, v3 = acc[mi][ni][3] + b1;
            if (mode == 0) {
                *(float2*)(C + (size_t)r * N + cix) = make_float2(v0, v1);
                *(float2*)(C + (size_t)(r + 8) * N + cix) = make_float2(v2, v3);
            } else {
                v0 = fmaxf(v0, 0.0f); v1 = fmaxf(v1, 0.0f);
                v2 = fmaxf(v2, 0.0f); v3 = fmaxf(v3, 0.0f);
                bf16 h0, l0, h1, l1;
                split1(v0, h0, l0); split1(v1, h1, l1);
                *(bf162*)(Ch + (size_t)r * N + cix) = bf162(h0, h1);
                *(bf162*)(Cl + (size_t)r * N + cix) = bf162(l0, l1);
                split1(v2, h0, l0); split1(v3, h1, l1);
                *(bf162*)(Ch + (size_t)(r + 8) * N + cix) = bf162(h0, h1);
                *(bf162*)(Cl + (size_t)(r + 8) * N + cix) = bf162(l0, l1);
            }
        }
    }
}

// ---------------- block reduce helper (128 threads) ------------------------------
__device__ __forceinline__ float2 block_reduce_2(float a, float b) {
    unsigned m = 0xffffffffu;
#pragma unroll
    for (int o = 16; o > 0; o >>= 1) {
        a += __shfl_down_sync(m, a, o);
        b += __shfl_down_sync(m, b, o);
    }
    __shared__ float sa[4], sb[4];
    int w = threadIdx.x >> 5, lane = threadIdx.x & 31;
    if (lane == 0) { sa[w] = a; sb[w] = b; }
    __syncthreads();
    if (threadIdx.x == 0) {
        float ta = sa[0] + sa[1] + sa[2] + sa[3];
        float tb = sb[0] + sb[1] + sb[2] + sb[3];
        sa[0] = ta; sb[0] = tb;
    }
    __syncthreads();
    return make_float2(sa[0], sb[0]);
}

// ---------------- GLU + residual + LayerNorm1 (also emits bf16 hi/lo) -------------
__global__ __launch_bounds__(128) void glu_ln_kernel(const float* __restrict__ z,
                                                     const float* __restrict__ x,
                                                     const float* __restrict__ g1,
                                                     const float* __restrict__ b1,
                                                     float* __restrict__ xln,
                                                     bf16* __restrict__ xh,
                                                     bf16* __restrict__ xl) {
    int row = blockIdx.x, tid = threadIdx.x;
    const float* zr = z + (size_t)row * (2 * HDIM);
    const float* xr = x + (size_t)row * HDIM;
    float v[4], s = 0.0f, s2 = 0.0f;
#pragma unroll
    for (int i = 0; i < 4; i++) {
        int c = tid + i * 128;
        float a = zr[c], g = zr[c + HDIM];
        float val = xr[c] + a / (1.0f + __expf(-g));
        v[i] = val; s += val; s2 += val * val;
    }
    float2 tot = block_reduce_2(s, s2);
    float mu = tot.x * (1.0f / HDIM);
    float var = tot.y * (1.0f / HDIM) - mu * mu;
    float rstd = rsqrtf(var + 1e-5f);
#pragma unroll
    for (int i = 0; i < 4; i++) {
        int c = tid + i * 128;
        float o = (v[i] - mu) * rstd * g1[c] + b1[c];
        xln[(size_t)row * HDIM + c] = o;
        bf16 hh, ll; split1(o, hh, ll);
        xh[(size_t)row * HDIM + c] = hh;
        xl[(size_t)row * HDIM + c] = ll;
    }
}

// ---------------- residual + LayerNorm2 (final output) ---------------------------
__global__ __launch_bounds__(128) void final_ln_kernel(const float* __restrict__ xln,
                                                       const float* __restrict__ y2,
                                                       const float* __restrict__ g2,
                                                       const float* __restrict__ b2,
                                                       float* __restrict__ out) {
    int row = blockIdx.x, tid = threadIdx.x;
    const float* a = xln + (size_t)row * HDIM;
    const float* b = y2 + (size_t)row * HDIM;
    float v[4], s = 0.0f, s2 = 0.0f;
#pragma unroll
    for (int i = 0; i < 4; i++) {
        int c = tid + i * 128;
        float val = a[c] + b[c];
        v[i] = val; s += val; s2 += val * val;
    }
    float2 tot = block_reduce_2(s, s2);
    float mu = tot.x * (1.0f / HDIM);
    float var = tot.y * (1.0f / HDIM) - mu * mu;
    float rstd = rsqrtf(var + 1e-5f);
#pragma unroll
    for (int i = 0; i < 4; i++) {
        int c = tid + i * 128;
        out[(size_t)row * HDIM + c] = (v[i] - mu) * rstd * g2[c] + b2[c];
    }
}

// ---------------- launch ----------------------------------------------------------
extern "C" void kernel_launch(void* const* d_in, const int* in_sizes, int n_in,
                              void* d_out, int out_size) {
    const float* x      = (const float*)d_in[0];
    const float* log_dt = (const float*)d_in[1];
    const float* A_re   = (const float*)d_in[2];
    const float* A_im   = (const float*)d_in[3];
    const float* C_re   = (const float*)d_in[4];
    const float* C_im   = (const float*)d_in[5];
    const float* D_skip = (const float*)d_in[6];
    const float* W_out  = (const float*)d_in[7];
    const float* b_out  = (const float*)d_in[8];
    const float* g1     = (const float*)d_in[9];
    const float* beta1  = (const float*)d_in[10];
    const float* g2     = (const float*)d_in[11];
    const float* beta2  = (const float*)d_in[12];
    const float* W1     = (const float*)d_in[13];
    const float* bc1    = (const float*)d_in[14];
    const float* W2     = (const float*)d_in[15];
    const float* bc2    = (const float*)d_in[16];
    float* out = (float*)d_out;

    bf16 *yh, *yl, *xh, *xl, *y1h, *y1l;
    bf16 *wouth, *woutl, *w1h, *w1l, *w2h, *w2l;
    float *z, *xln, *y2;
    cudaGetSymbolAddress((void**)&yh,  g_yh);
    cudaGetSymbolAddress((void**)&yl,  g_yl);
    cudaGetSymbolAddress((void**)&z,   g_z);
    cudaGetSymbolAddress((void**)&xln, g_xln);
    cudaGetSymbolAddress((void**)&xh,  g_xh);
    cudaGetSymbolAddress((void**)&xl,  g_xl);
    cudaGetSymbolAddress((void**)&y1h, g_y1h);
    cudaGetSymbolAddress((void**)&y1l, g_y1l);
    cudaGetSymbolAddress((void**)&y2,  g_y2);
    cudaGetSymbolAddress((void**)&wouth, g_wouth);
    cudaGetSymbolAddress((void**)&woutl, g_woutl);
    cudaGetSymbolAddress((void**)&w1h, g_w1h);
    cudaGetSymbolAddress((void**)&w1l, g_w1l);
    cudaGetSymbolAddress((void**)&w2h, g_w2h);
    cudaGetSymbolAddress((void**)&w2l, g_w2l);

    cudaFuncSetAttribute(gemm_mma, cudaFuncAttributeMaxDynamicSharedMemorySize, GEMM_SMEM);

    // 0) split weights to bf16 hi/lo (one-shot per call, tiny)
    split_kernel<<<(2 * HDIM * HDIM + 255) / 256, 256>>>(W_out, wouth, woutl, 2 * HDIM * HDIM);
    split_kernel<<<(HDIM * HDIM + 255) / 256, 256>>>(W1, w1h, w1l, HDIM * HDIM);
    split_kernel<<<(HDIM * HDIM + 255) / 256, 256>>>(W2, w2h, w2l, HDIM * HDIM);

    // 1) discretize SSM params
    precompute_kernel<<<HDIM, NST>>>(log_dt, A_re, A_im, C_re, C_im);

    // 2) SSM recurrence + D skip + gelu -> yact (bf16 hi/lo)
    scan_kernel<<<(BSZ * HDIM * 8) / 256, 256>>>(x, D_skip, yh, yl);

    // 3) GLU projection: z = yact @ W_out^T + b_out
    gemm_mma<<<dim3((2 * HDIM) / 128, ROWS / 128), 256, GEMM_SMEM>>>(
        yh, yl, wouth, woutl, b_out, z, nullptr, nullptr, HDIM, 2 * HDIM, 0);

    // 4) GLU + residual + LN1 -> xln (fp32 + bf16 hi/lo)
    glu_ln_kernel<<<ROWS, 128>>>(z, x, g1, beta1, xln, xh, xl);

    // 5) FFN: y1 = relu(xln @ W1^T + bc1) -> bf16 hi/lo directly
    gemm_mma<<<dim3(HDIM / 128, ROWS / 128), 256, GEMM_SMEM>>>(
        xh, xl, w1h, w1l, bc1, nullptr, y1h, y1l, HDIM, HDIM, 1);

    // 6) y2 = y1 @ W2^T + bc2
    gemm_mma<<<dim3(HDIM / 128, ROWS / 128), 256, GEMM_SMEM>>>(
        y1h, y1l, w2h, w2l, bc2, y2, nullptr, nullptr, HDIM, HDIM, 0);

    // 7) out = LN2(xln + y2)
    final_ln_kernel<<<ROWS, 128>>>(xln, y2, g2, beta2, out);
}

// round 5
// speedup vs baseline: 2.2151x; 1.0503x over previous
#include <cuda_runtime.h>
#include <cuda_bf16.h>
#include <math.h>
#include <stdint.h>

#define BSZ   8
#define LSEQ  2048
#define HDIM  512
#define NST   64
#define ROWS  (BSZ*LSEQ)      // 16384

typedef __nv_bfloat16 bf16;
typedef __nv_bfloat162 bf162;

// ---------------- scratch (device globals; no allocation allowed) ----------------
__device__ float g_wre[HDIM*NST];
__device__ float g_wim[HDIM*NST];
__device__ float g_ctre[HDIM*NST];
__device__ float g_ctim[HDIM*NST];

__device__ bf16  g_yh [(size_t)ROWS*HDIM];
__device__ bf16  g_yl [(size_t)ROWS*HDIM];
__device__ float g_z  [(size_t)ROWS*2*HDIM];
__device__ float g_xln[(size_t)ROWS*HDIM];
__device__ bf16  g_xh [(size_t)ROWS*HDIM];
__device__ bf16  g_xl [(size_t)ROWS*HDIM];
__device__ bf16  g_y1h[(size_t)ROWS*HDIM];
__device__ bf16  g_y1l[(size_t)ROWS*HDIM];
__device__ float g_y2 [(size_t)ROWS*HDIM];

__device__ bf16 g_wouth[2*HDIM*HDIM];
__device__ bf16 g_woutl[2*HDIM*HDIM];
__device__ bf16 g_w1h[HDIM*HDIM];
__device__ bf16 g_w1l[HDIM*HDIM];
__device__ bf16 g_w2h[HDIM*HDIM];
__device__ bf16 g_w2l[HDIM*HDIM];

// =============================== helpers =========================================
__device__ __forceinline__ uint32_t smem_u32(const void* p) {
    uint32_t a;
    asm("{ .reg .u64 t; cvta.to.shared.u64 t, %1; cvt.u32.u64 %0, t; }" : "=r"(a) : "l"(p));
    return a;
}

__device__ __forceinline__ void ldmatrix_x4(uint32_t* r, uint32_t addr) {
    asm volatile("ldmatrix.sync.aligned.m8n8.x4.shared.b16 {%0,%1,%2,%3}, [%4];"
        : "=r"(r[0]), "=r"(r[1]), "=r"(r[2]), "=r"(r[3]) : "r"(addr));
}

__device__ __forceinline__ void mma_bf16(float* c, const uint32_t* a,
                                         uint32_t b0, uint32_t b1) {
    asm volatile("mma.sync.aligned.m16n8k16.row.col.f32.bf16.bf16.f32 "
        "{%0,%1,%2,%3}, {%4,%5,%6,%7}, {%8,%9}, {%0,%1,%2,%3};"
        : "+f"(c[0]), "+f"(c[1]), "+f"(c[2]), "+f"(c[3])
        : "r"(a[0]), "r"(a[1]), "r"(a[2]), "r"(a[3]), "r"(b0), "r"(b1));
}

#define CP_ASYNC16(saddr, gaddr) \
    asm volatile("cp.async.cg.shared.global [%0], [%1], 16;" \
                 :: "r"(saddr), "l"(gaddr) : "memory")
#define CP_COMMIT() asm volatile("cp.async.commit_group;" ::: "memory")
#define CP_WAIT(n)  asm volatile("cp.async.wait_group %0;" :: "n"(n) : "memory")

__device__ __forceinline__ void split1(float v, bf16& h, bf16& l) {
    h = __float2bfloat16(v);
    l = __float2bfloat16(v - __bfloat162float(h));
}

// ---------------- weight split (all three weights in one launch) -----------------
__global__ void split_all_kernel(const float* __restrict__ wout,
                                 const float* __restrict__ w1,
                                 const float* __restrict__ w2) {
    int i = blockIdx.x * blockDim.x + threadIdx.x;
    const int n1 = 2 * HDIM * HDIM;      // wout
    const int n2 = HDIM * HDIM;          // w1 / w2
    if (i < n1) {
        bf16 h, l; split1(wout[i], h, l);
        g_wouth[i] = h; g_woutl[i] = l;
    } else if (i < n1 + n2) {
        int j = i - n1;
        bf16 h, l; split1(w1[j], h, l);
        g_w1h[j] = h; g_w1l[j] = l;
    } else {
        int j = i - n1 - n2;
        bf16 h, l; split1(w2[j], h, l);
        g_w2h[j] = h; g_w2l[j] = l;
    }
}

// ---------------- precompute w = exp(dt*A), Ct = C*(exp(dt*A)-1)/A ----------------
__global__ void precompute_kernel(const float* __restrict__ log_dt,
                                  const float* __restrict__ Are,
                                  const float* __restrict__ Aim,
                                  const float* __restrict__ Cre,
                                  const float* __restrict__ Cim) {
    int h = blockIdx.x, n = threadIdx.x;
    int idx = h * NST + n;
    float dt = expf(log_dt[h]);
    float ar = Are[idx] * dt;
    float ai = Aim[idx] * dt;
    float e  = expf(ar);
    float sb, cb;
    sincosf(ai, &sb, &cb);
    float wre = e * cb, wim = e * sb;
    float Ere = wre - 1.0f, Eim = wim;
    float Ar = Are[idx], Ai = Aim[idx];
    float inv = 1.0f / (Ar * Ar + Ai * Ai);
    float rre = (Ere * Ar + Eim * Ai) * inv;
    float rim = (Eim * Ar - Ere * Ai) * inv;
    float cr = Cre[idx], ci = Cim[idx];
    g_ctre[idx] = cr * rre - ci * rim;
    g_ctim[idx] = cr * rim + ci * rre;
    g_wre[idx]  = wre;
    g_wim[idx]  = wim;
}

// ---------------- SSM scan ---------------------------------------------------------
#define PF 8
__global__ __launch_bounds__(256) void scan_kernel(const float* __restrict__ x,
                                                   const float* __restrict__ Dskip,
                                                   bf16* __restrict__ yh,
                                                   bf16* __restrict__ yl) {
    int tid  = threadIdx.x;
    int gid  = blockIdx.x * (blockDim.x / 8) + (tid >> 3);
    int lane = tid & 7;
    int b = gid >> 9;
    int h = gid & (HDIM - 1);

    float wre[8], wim[8], cre[8], cim[8], sre[8], sim[8];
    int base = h * NST + lane * 8;
#pragma unroll
    for (int j = 0; j < 8; j++) {
        wre[j] = g_wre[base + j];
        wim[j] = g_wim[base + j];
        cre[j] = g_ctre[base + j];
        cim[j] = g_ctim[base + j];
        sre[j] = 0.0f; sim[j] = 0.0f;
    }
    float Dv = Dskip[h];
    const float* xp = x + (size_t)b * LSEQ * HDIM + h;
    size_t orow = (size_t)b * LSEQ * HDIM + h;

    float ubuf[PF];
#pragma unroll
    for (int i = 0; i < PF; i++) ubuf[i] = __ldg(xp + (size_t)i * HDIM);

#pragma unroll 8
    for (int l = 0; l < LSEQ; l++) {
        float u = ubuf[l & (PF - 1)];
        if (l + PF < LSEQ) ubuf[l & (PF - 1)] = __ldg(xp + (size_t)(l + PF) * HDIM);
        float acc = 0.0f;
#pragma unroll
        for (int j = 0; j < 8; j++) {
            float nr = fmaf(wre[j], sre[j], fmaf(-wim[j], sim[j], u));
            float ni = fmaf(wim[j], sre[j], wre[j] * sim[j]);
            sre[j] = nr; sim[j] = ni;
            acc = fmaf(cre[j], nr, acc);
            acc = fmaf(-cim[j], ni, acc);
        }
        acc += __shfl_xor_sync(0xffffffffu, acc, 1);
        acc += __shfl_xor_sync(0xffffffffu, acc, 2);
        acc += __shfl_xor_sync(0xffffffffu, acc, 4);
        if (lane == 0) {
            float v = 2.0f * acc + Dv * u;
            float c = 0.7978845608028654f * (v + 0.044715f * v * v * v);
            float gv = v / (1.0f + __expf(-2.0f * c));
            bf16 hh, ll; split1(gv, hh, ll);
            yh[orow + (size_t)l * HDIM] = hh;
            yl[orow + (size_t)l * HDIM] = ll;
        }
    }
}

// ======================= mma.sync split-bf16 GEMM, cp.async 3-stage ===============
#define LDSB   80                   // bytes per smem tile row (32 bf16 + 8 pad)
#define TILEB  (128 * LDSB)         // 10240 bytes per tile
#define STAGEB (4 * TILEB)          // Ah, Al, Bh, Bl
#define NSTAGE 3
#define GEMM_SMEM (NSTAGE * STAGEB) // 122880 bytes

__global__ void __launch_bounds__(256, 1)
gemm_mma(const bf16* __restrict__ Ah, const bf16* __restrict__ Al,
         const bf16* __restrict__ Bh, const bf16* __restrict__ Bl,
         const float* __restrict__ bias,
         float* __restrict__ C, bf16* __restrict__ Ch, bf16* __restrict__ Cl,
         int K, int N, int mode) {
    extern __shared__ char smem[];
    uint32_t sbase = smem_u32(smem);
    int tid = threadIdx.x, wid = tid >> 5, lane = tid & 31;
    int row0 = blockIdx.y * 128, col0 = blockIdx.x * 128;
    int wm = wid >> 1, wn = wid & 1;

    float acc[2][8][4];
#pragma unroll
    for (int i = 0; i < 2; i++)
#pragma unroll
        for (int j = 0; j < 8; j++)
#pragma unroll
            for (int q = 0; q < 4; q++) acc[i][j][q] = 0.0f;

    // load mapping: 2 threads per row, each thread 2x16B
    int lr = tid >> 1;
    int lc = (tid & 1) * 16;                   // bf16 elements
    const bf16* aph = Ah + (size_t)(row0 + lr) * K + lc;
    const bf16* apl = Al + (size_t)(row0 + lr) * K + lc;
    const bf16* bph = Bh + (size_t)(col0 + lr) * K + lc;
    const bf16* bpl = Bl + (size_t)(col0 + lr) * K + lc;
    uint32_t soff = (uint32_t)(lr * LDSB + lc * 2);

    int nch = K / 32;

    // issue one chunk's loads into stage s
    auto issue = [&](int c, int s) {
        uint32_t st = sbase + (uint32_t)s * STAGEB;
        int go = c * 32;
        uint32_t ah = st + soff;
        CP_ASYNC16(ah,              aph + go);
        CP_ASYNC16(ah + 16,         aph + go + 8);
        CP_ASYNC16(ah + TILEB,      apl + go);
        CP_ASYNC16(ah + TILEB + 16, apl + go + 8);
        uint32_t bh = st + 2 * TILEB + soff;
        CP_ASYNC16(bh,              bph + go);
        CP_ASYNC16(bh + 16,         bph + go + 8);
        CP_ASYNC16(bh + TILEB,      bpl + go);
        CP_ASYNC16(bh + TILEB + 16, bpl + go + 8);
    };

    // prologue: fill stages 0..NSTAGE-2
#pragma unroll
    for (int s = 0; s < NSTAGE - 1; ++s) {
        if (s < nch) issue(s, s);
        CP_COMMIT();
    }

    int r_lm = (lane & 7) + ((lane >> 3) & 1) * 8;
    int k_lm = ((lane >> 4) & 1) * 8;

    for (int c = 0; c < nch; ++c) {
        // issue chunk c+NSTAGE-1 into its stage (overwrites stage read at iter c-1;
        // safe: post-compute __syncthreads from previous iteration)
        int cn = c + NSTAGE - 1;
        if (cn < nch) issue(cn, cn % NSTAGE);
        CP_COMMIT();
        CP_WAIT(NSTAGE - 1);      // chunk c complete
        __syncthreads();

        uint32_t st = sbase + (uint32_t)(c % NSTAGE) * STAGEB;
        uint32_t ahs = st;
        uint32_t bhs = st + 2 * TILEB;

#pragma unroll
        for (int ks = 0; ks < 2; ++ks) {
            uint32_t afh[2][4], afl[2][4], bfh[4][4], bfl[4][4];
            int kcol = ks * 16 + k_lm;
#pragma unroll
            for (int mi = 0; mi < 2; ++mi) {
                int m = wm * 32 + mi * 16 + r_lm;
                uint32_t ad = ahs + (uint32_t)(m * LDSB + kcol * 2);
                ldmatrix_x4(afh[mi], ad);
                ldmatrix_x4(afl[mi], ad + TILEB);
            }
#pragma unroll
            for (int nj = 0; nj < 4; ++nj) {
                int n = wn * 64 + nj * 16 + r_lm;
                uint32_t bd = bhs + (uint32_t)(n * LDSB + kcol * 2);
                ldmatrix_x4(bfh[nj], bd);
                ldmatrix_x4(bfl[nj], bd + TILEB);
            }
#pragma unroll
            for (int mi = 0; mi < 2; ++mi)
#pragma unroll
                for (int nj = 0; nj < 4; ++nj)
#pragma unroll
                    for (int h = 0; h < 2; ++h) {
                        float* cc = acc[mi][nj * 2 + h];
                        mma_bf16(cc, afh[mi], bfh[nj][h], bfh[nj][2 + h]);
                        mma_bf16(cc, afh[mi], bfl[nj][h], bfl[nj][2 + h]);
                        mma_bf16(cc, afl[mi], bfh[nj][h], bfh[nj][2 + h]);
                    }
        }
        __syncthreads();          // all warps done reading stage c%NSTAGE
    }

    // epilogue
    int tg = lane >> 2, tq = lane & 3;
#pragma unroll
    for (int mi = 0; mi < 2; ++mi) {
        int r = row0 + wm * 32 + mi * 16 + tg;
#pragma unroll
        for (int ni = 0; ni < 8; ++ni) {
            int cix = col0 + wn * 64 + ni * 8 + tq * 2;
            float b0 = bias[cix], b1 = bias[cix + 1];
            float v0 = acc[mi][ni][0] + b0, v1 = acc[mi][ni][1] + b1;
            float v2 = acc[mi][ni][2] + b0, v3 = acc[mi][ni][3] + b1;
            if (mode == 0) {
                *(float2*)(C + (size_t)r * N + cix) = make_float2(v0, v1);
                *(float2*)(C + (size_t)(r + 8) * N + cix) = make_float2(v2, v3);
            } else {
                v0 = fmaxf(v0, 0.0f); v1 = fmaxf(v1, 0.0f);
                v2 = fmaxf(v2, 0.0f); v3 = fmaxf(v3, 0.0f);
                bf16 h0, l0, h1, l1;
                split1(v0, h0, l0); split1(v1, h1, l1);
                *(bf162*)(Ch + (size_t)r * N + cix) = bf162(h0, h1);
                *(bf162*)(Cl + (size_t)r * N + cix) = bf162(l0, l1);
                split1(v2, h0, l0); split1(v3, h1, l1);
                *(bf162*)(Ch + (size_t)(r + 8) * N + cix) = bf162(h0, h1);
                *(bf162*)(Cl + (size_t)(r + 8) * N + cix) = bf162(l0, l1);
            }
        }
    }
}

// ---------------- block reduce helper (128 threads) ------------------------------
__device__ __forceinline__ float2 block_reduce_2(float a, float b) {
    unsigned m = 0xffffffffu;
#pragma unroll
    for (int o = 16; o > 0; o >>= 1) {
        a += __shfl_down_sync(m, a, o);
        b += __shfl_down_sync(m, b, o);
    }
    __shared__ float sa[4], sb[4];
    int w = threadIdx.x >> 5, lane = threadIdx.x & 31;
    if (lane == 0) { sa[w] = a; sb[w] = b; }
    __syncthreads();
    if (threadIdx.x == 0) {
        float ta = sa[0] + sa[1] + sa[2] + sa[3];
        float tb = sb[0] + sb[1] + sb[2] + sb[3];
        sa[0] = ta; sb[0] = tb;
    }
    __syncthreads();
    return make_float2(sa[0], sb[0]);
}

// ---------------- GLU + residual + LayerNorm1 (emits bf16 hi/lo) ------------------
__global__ __launch_bounds__(128) void glu_ln_kernel(const float* __restrict__ z,
                                                     const float* __restrict__ x,
                                                     const float* __restrict__ g1,
                                                     const float* __restrict__ b1,
                                                     float* __restrict__ xln,
                                                     bf16* __restrict__ xh,
                                                     bf16* __restrict__ xl) {
    int row = blockIdx.x, tid = threadIdx.x;
    const float* zr = z + (size_t)row * (2 * HDIM);
    const float* xr = x + (size_t)row * HDIM;
    float v[4], s = 0.0f, s2 = 0.0f;
#pragma unroll
    for (int i = 0; i < 4; i++) {
        int c = tid + i * 128;
        float a = zr[c], g = zr[c + HDIM];
        float val = xr[c] + a / (1.0f + __expf(-g));
        v[i] = val; s += val; s2 += val * val;
    }
    float2 tot = block_reduce_2(s, s2);
    float mu = tot.x * (1.0f / HDIM);
    float var = tot.y * (1.0f / HDIM) - mu * mu;
    float rstd = rsqrtf(var + 1e-5f);
#pragma unroll
    for (int i = 0; i < 4; i++) {
        int c = tid + i * 128;
        float o = (v[i] - mu) * rstd * g1[c] + b1[c];
        xln[(size_t)row * HDIM + c] = o;
        bf16 hh, ll; split1(o, hh, ll);
        xh[(size_t)row * HDIM + c] = hh;
        xl[(size_t)row * HDIM + c] = ll;
    }
}

// ---------------- residual + LayerNorm2 (final output) ---------------------------
__global__ __launch_bounds__(128) void final_ln_kernel(const float* __restrict__ xln,
                                                       const float* __restrict__ y2,
                                                       const float* __restrict__ g2,
                                                       const float* __restrict__ b2,
                                                       float* __restrict__ out) {
    int row = blockIdx.x, tid = threadIdx.x;
    const float* a = xln + (size_t)row * HDIM;
    const float* b = y2 + (size_t)row * HDIM;
    float v[4], s = 0.0f, s2 = 0.0f;
#pragma unroll
    for (int i = 0; i < 4; i++) {
        int c = tid + i * 128;
        float val = a[c] + b[c];
        v[i] = val; s += val; s2 += val * val;
    }
    float2 tot = block_reduce_2(s, s2);
    float mu = tot.x * (1.0f / HDIM);
    float var = tot.y * (1.0f / HDIM) - mu * mu;
    float rstd = rsqrtf(var + 1e-5f);
#pragma unroll
    for (int i = 0; i < 4; i++) {
        int c = tid + i * 128;
        out[(size_t)row * HDIM + c] = (v[i] - mu) * rstd * g2[c] + b2[c];
    }
}

// ---------------- launch ----------------------------------------------------------
extern "C" void kernel_launch(void* const* d_in, const int* in_sizes, int n_in,
                              void* d_out, int out_size) {
    const float* x      = (const float*)d_in[0];
    const float* log_dt = (const float*)d_in[1];
    const float* A_re   = (const float*)d_in[2];
    const float* A_im   = (const float*)d_in[3];
    const float* C_re   = (const float*)d_in[4];
    const float* C_im   = (const float*)d_in[5];
    const float* D_skip = (const float*)d_in[6];
    const float* W_out  = (const float*)d_in[7];
    const float* b_out  = (const float*)d_in[8];
    const float* g1     = (const float*)d_in[9];
    const float* beta1  = (const float*)d_in[10];
    const float* g2     = (const float*)d_in[11];
    const float* beta2  = (const float*)d_in[12];
    const float* W1     = (const float*)d_in[13];
    const float* bc1    = (const float*)d_in[14];
    const float* W2     = (const float*)d_in[15];
    const float* bc2    = (const float*)d_in[16];
    float* out = (float*)d_out;

    bf16 *yh, *yl, *xh, *xl, *y1h, *y1l;
    bf16 *wouth, *woutl, *w1h, *w1l, *w2h, *w2l;
    float *z, *xln, *y2;
    cudaGetSymbolAddress((void**)&yh,  g_yh);
    cudaGetSymbolAddress((void**)&yl,  g_yl);
    cudaGetSymbolAddress((void**)&z,   g_z);
    cudaGetSymbolAddress((void**)&xln, g_xln);
    cudaGetSymbolAddress((void**)&xh,  g_xh);
    cudaGetSymbolAddress((void**)&xl,  g_xl);
    cudaGetSymbolAddress((void**)&y1h, g_y1h);
    cudaGetSymbolAddress((void**)&y1l, g_y1l);
    cudaGetSymbolAddress((void**)&y2,  g_y2);
    cudaGetSymbolAddress((void**)&wouth, g_wouth);
    cudaGetSymbolAddress((void**)&woutl, g_woutl);
    cudaGetSymbolAddress((void**)&w1h, g_w1h);
    cudaGetSymbolAddress((void**)&w1l, g_w1l);
    cudaGetSymbolAddress((void**)&w2h, g_w2h);
    cudaGetSymbolAddress((void**)&w2l, g_w2l);

    cudaFuncSetAttribute(gemm_mma, cudaFuncAttributeMaxDynamicSharedMemorySize, GEMM_SMEM);

    // 1) discretize SSM params
    precompute_kernel<<<HDIM, NST>>>(log_dt, A_re, A_im, C_re, C_im);

    // 2) SSM recurrence + D skip + gelu -> yact (bf16 hi/lo)
    scan_kernel<<<(BSZ * HDIM * 8) / 256, 256>>>(x, D_skip, yh, yl);

    // 3) split all weights (one launch)
    split_all_kernel<<<(4 * HDIM * HDIM + 255) / 256, 256>>>(W_out, W1, W2);

    // 4) GLU projection (this is the profiled launch slot)
    gemm_mma<<<dim3((2 * HDIM) / 128, ROWS / 128), 256, GEMM_SMEM>>>(
        yh, yl, wouth, woutl, b_out, z, nullptr, nullptr, HDIM, 2 * HDIM, 0);

    // 5) GLU + residual + LN1 -> xln (fp32 + bf16 hi/lo)
    glu_ln_kernel<<<ROWS, 128>>>(z, x, g1, beta1, xln, xh, xl);

    // 6) FFN: y1 = relu(xln @ W1^T + bc1) -> bf16 hi/lo
    gemm_mma<<<dim3(HDIM / 128, ROWS / 128), 256, GEMM_SMEM>>>(
        xh, xl, w1h, w1l, bc1, nullptr, y1h, y1l, HDIM, HDIM, 1);

    // 7) y2 = y1 @ W2^T + bc2
    gemm_mma<<<dim3(HDIM / 128, ROWS / 128), 256, GEMM_SMEM>>>(
        y1h, y1l, w2h, w2l, bc2, y2, nullptr, nullptr, HDIM, HDIM, 0);

    // 8) out = LN2(xln + y2)
    final_ln_kernel<<<ROWS, 128>>>(xln, y2, g2, beta2, out);
}

// round 6
// speedup vs baseline: 2.5093x; 1.1328x over previous
#include <cuda_runtime.h>
#include <cuda_bf16.h>
#include <math.h>
#include <stdint.h>

#define BSZ   8
#define LSEQ  2048
#define HDIM  512
#define NST   64
#define ROWS  (BSZ*LSEQ)      // 16384
#define SEG   16              // segments for chunked scan
#define SEGT  (LSEQ/SEG)      // 128 steps per segment

typedef __nv_bfloat16 bf16;
typedef __nv_bfloat162 bf162;

// ---------------- scratch (device globals; no allocation allowed) ----------------
__device__ float g_wre[HDIM*NST];
__device__ float g_wim[HDIM*NST];
__device__ float g_wTre[HDIM*NST];    // w^SEGT
__device__ float g_wTim[HDIM*NST];
__device__ float g_ctre[HDIM*NST];
__device__ float g_ctim[HDIM*NST];

__device__ float g_sendre[(size_t)BSZ*HDIM*SEG*NST];  // segment end states
__device__ float g_sendim[(size_t)BSZ*HDIM*SEG*NST];
__device__ float g_carre [(size_t)BSZ*HDIM*SEG*NST];  // segment carry-in states
__device__ float g_carim [(size_t)BSZ*HDIM*SEG*NST];

__device__ bf16  g_yh [(size_t)ROWS*HDIM];
__device__ bf16  g_yl [(size_t)ROWS*HDIM];
__device__ float g_z  [(size_t)ROWS*2*HDIM];
__device__ float g_xln[(size_t)ROWS*HDIM];
__device__ bf16  g_xh [(size_t)ROWS*HDIM];
__device__ bf16  g_xl [(size_t)ROWS*HDIM];
__device__ bf16  g_y1h[(size_t)ROWS*HDIM];
__device__ bf16  g_y1l[(size_t)ROWS*HDIM];
__device__ float g_y2 [(size_t)ROWS*HDIM];

__device__ bf16 g_wouth[2*HDIM*HDIM];
__device__ bf16 g_woutl[2*HDIM*HDIM];
__device__ bf16 g_w1h[HDIM*HDIM];
__device__ bf16 g_w1l[HDIM*HDIM];
__device__ bf16 g_w2h[HDIM*HDIM];
__device__ bf16 g_w2l[HDIM*HDIM];

// =============================== helpers =========================================
__device__ __forceinline__ uint32_t smem_u32(const void* p) {
    uint32_t a;
    asm("{ .reg .u64 t; cvta.to.shared.u64 t, %1; cvt.u32.u64 %0, t; }" : "=r"(a) : "l"(p));
    return a;
}

__device__ __forceinline__ void ldmatrix_x4(uint32_t* r, uint32_t addr) {
    asm volatile("ldmatrix.sync.aligned.m8n8.x4.shared.b16 {%0,%1,%2,%3}, [%4];"
        : "=r"(r[0]), "=r"(r[1]), "=r"(r[2]), "=r"(r[3]) : "r"(addr));
}

__device__ __forceinline__ void mma_bf16(float* c, const uint32_t* a,
                                         uint32_t b0, uint32_t b1) {
    asm volatile("mma.sync.aligned.m16n8k16.row.col.f32.bf16.bf16.f32 "
        "{%0,%1,%2,%3}, {%4,%5,%6,%7}, {%8,%9}, {%0,%1,%2,%3};"
        : "+f"(c[0]), "+f"(c[1]), "+f"(c[2]), "+f"(c[3])
        : "r"(a[0]), "r"(a[1]), "r"(a[2]), "r"(a[3]), "r"(b0), "r"(b1));
}

#define CP_ASYNC16(saddr, gaddr) \
    asm volatile("cp.async.cg.shared.global [%0], [%1], 16;" \
                 :: "r"(saddr), "l"(gaddr) : "memory")
#define CP_COMMIT() asm volatile("cp.async.commit_group;" ::: "memory")
#define CP_WAIT(n)  asm volatile("cp.async.wait_group %0;" :: "n"(n) : "memory")

__device__ __forceinline__ void split1(float v, bf16& h, bf16& l) {
    h = __float2bfloat16(v);
    l = __float2bfloat16(v - __bfloat162float(h));
}

// ---------------- weight split (all three weights in one launch) -----------------
__global__ void split_all_kernel(const float* __restrict__ wout,
                                 const float* __restrict__ w1,
                                 const float* __restrict__ w2) {
    int i = blockIdx.x * blockDim.x + threadIdx.x;
    const int n1 = 2 * HDIM * HDIM;
    const int n2 = HDIM * HDIM;
    if (i < n1) {
        bf16 h, l; split1(wout[i], h, l);
        g_wouth[i] = h; g_woutl[i] = l;
    } else if (i < n1 + n2) {
        int j = i - n1;
        bf16 h, l; split1(w1[j], h, l);
        g_w1h[j] = h; g_w1l[j] = l;
    } else {
        int j = i - n1 - n2;
        bf16 h, l; split1(w2[j], h, l);
        g_w2h[j] = h; g_w2l[j] = l;
    }
}

// ---------------- precompute w, w^SEGT, Ct -----------------------------------------
__global__ void precompute_kernel(const float* __restrict__ log_dt,
                                  const float* __restrict__ Are,
                                  const float* __restrict__ Aim,
                                  const float* __restrict__ Cre,
                                  const float* __restrict__ Cim) {
    int h = blockIdx.x, n = threadIdx.x;
    int idx = h * NST + n;
    float dt = expf(log_dt[h]);
    float ar = Are[idx] * dt;
    float ai = Aim[idx] * dt;
    float e  = expf(ar);
    float sb, cb;
    sincosf(ai, &sb, &cb);
    float wre = e * cb, wim = e * sb;
    // w^SEGT = exp(dtA * SEGT)
    float eT = expf(ar * (float)SEGT);
    float sT, cT;
    sincosf(ai * (float)SEGT, &sT, &cT);
    g_wTre[idx] = eT * cT;
    g_wTim[idx] = eT * sT;

    float Ere = wre - 1.0f, Eim = wim;
    float Ar = Are[idx], Ai = Aim[idx];
    float inv = 1.0f / (Ar * Ar + Ai * Ai);
    float rre = (Ere * Ar + Eim * Ai) * inv;
    float rim = (Eim * Ar - Ere * Ai) * inv;
    float cr = Cre[idx], ci = Cim[idx];
    g_ctre[idx] = cr * rre - ci * rim;
    g_ctim[idx] = cr * rim + ci * rre;
    g_wre[idx]  = wre;
    g_wim[idx]  = wim;
}

// ---------------- chunked scan pass 1: zero-init end state per segment ------------
// groups (b,h,seg) for seg in 0..SEG-2 ; 8 lanes/group, 8 states/lane
#define PF1 4
__global__ __launch_bounds__(256) void scan_part1(const float* __restrict__ x) {
    int tid  = threadIdx.x;
    int gid  = blockIdx.x * 32 + (tid >> 3);     // 0 .. 8*512*15-1
    int lane = tid & 7;
    int seg  = gid % (SEG - 1);
    int rem  = gid / (SEG - 1);
    int h = rem & (HDIM - 1);
    int b = rem >> 9;

    float wre[8], wim[8], sre[8], sim[8];
    int base = h * NST + lane * 8;
#pragma unroll
    for (int j = 0; j < 8; j++) {
        wre[j] = g_wre[base + j];
        wim[j] = g_wim[base + j];
        sre[j] = 0.0f; sim[j] = 0.0f;
    }
    const float* xp = x + ((size_t)b * LSEQ + seg * SEGT) * HDIM + h;

    float ubuf[PF1];
#pragma unroll
    for (int i = 0; i < PF1; i++) ubuf[i] = __ldg(xp + (size_t)i * HDIM);

#pragma unroll 4
    for (int l = 0; l < SEGT; l++) {
        float u = ubuf[l & (PF1 - 1)];
        if (l + PF1 < SEGT) ubuf[l & (PF1 - 1)] = __ldg(xp + (size_t)(l + PF1) * HDIM);
#pragma unroll
        for (int j = 0; j < 8; j++) {
            float nr = fmaf(wre[j], sre[j], fmaf(-wim[j], sim[j], u));
            float ni = fmaf(wim[j], sre[j], wre[j] * sim[j]);
            sre[j] = nr; sim[j] = ni;
        }
    }

    size_t ob = (((size_t)(b * HDIM + h) * SEG) + seg) * NST + lane * 8;
#pragma unroll
    for (int j = 0; j < 8; j++) {
        g_sendre[ob + j] = sre[j];
        g_sendim[ob + j] = sim[j];
    }
}

// ---------------- chunked scan combine: carry[j+1] = w^T carry[j] + send[j] -------
__global__ __launch_bounds__(256) void scan_combine() {
    int idx = blockIdx.x * blockDim.x + threadIdx.x;    // 0 .. 8*512*64-1
    int n = idx & (NST - 1);
    int rem = idx >> 6;
    int h = rem & (HDIM - 1);
    int b = rem >> 9;
    float wTre = g_wTre[h * NST + n];
    float wTim = g_wTim[h * NST + n];
    float cr = 0.0f, ci = 0.0f;
    size_t base = ((size_t)(b * HDIM + h) * SEG) * NST + n;
#pragma unroll
    for (int j = 0; j < SEG; j++) {
        g_carre[base + (size_t)j * NST] = cr;
        g_carim[base + (size_t)j * NST] = ci;
        if (j < SEG - 1) {
            float er = g_sendre[base + (size_t)j * NST];
            float ei = g_sendim[base + (size_t)j * NST];
            float nr = fmaf(wTre, cr, fmaf(-wTim, ci, er));
            float ni = fmaf(wTim, cr, fmaf(wTre, ci, ei));
            cr = nr; ci = ni;
        }
    }
}

// ---------------- chunked scan pass 2: full recurrence per segment ----------------
#define PF2 4
__global__ __launch_bounds__(256) void scan_part2(const float* __restrict__ x,
                                                  const float* __restrict__ Dskip,
                                                  bf16* __restrict__ yh,
                                                  bf16* __restrict__ yl) {
    int tid  = threadIdx.x;
    int gid  = blockIdx.x * 32 + (tid >> 3);     // 0 .. 8*512*16-1
    int lane = tid & 7;
    int seg  = gid & (SEG - 1);
    int rem  = gid >> 4;
    int h = rem & (HDIM - 1);
    int b = rem >> 9;

    float wre[8], wim[8], cre[8], cim[8], sre[8], sim[8];
    int base = h * NST + lane * 8;
    size_t cb = (((size_t)(b * HDIM + h) * SEG) + seg) * NST + lane * 8;
#pragma unroll
    for (int j = 0; j < 8; j++) {
        wre[j] = g_wre[base + j];
        wim[j] = g_wim[base + j];
        cre[j] = g_ctre[base + j];
        cim[j] = g_ctim[base + j];
        sre[j] = g_carre[cb + j];
        sim[j] = g_carim[cb + j];
    }
    float Dv = Dskip[h];
    const float* xp = x + ((size_t)b * LSEQ + seg * SEGT) * HDIM + h;
    size_t orow = ((size_t)b * LSEQ + seg * SEGT) * HDIM + h;

    float ubuf[PF2];
#pragma unroll
    for (int i = 0; i < PF2; i++) ubuf[i] = __ldg(xp + (size_t)i * HDIM);

#pragma unroll 4
    for (int l = 0; l < SEGT; l++) {
        float u = ubuf[l & (PF2 - 1)];
        if (l + PF2 < SEGT) ubuf[l & (PF2 - 1)] = __ldg(xp + (size_t)(l + PF2) * HDIM);
        float acc = 0.0f;
#pragma unroll
        for (int j = 0; j < 8; j++) {
            float nr = fmaf(wre[j], sre[j], fmaf(-wim[j], sim[j], u));
            float ni = fmaf(wim[j], sre[j], wre[j] * sim[j]);
            sre[j] = nr; sim[j] = ni;
            acc = fmaf(cre[j], nr, acc);
            acc = fmaf(-cim[j], ni, acc);
        }
        acc += __shfl_xor_sync(0xffffffffu, acc, 1);
        acc += __shfl_xor_sync(0xffffffffu, acc, 2);
        acc += __shfl_xor_sync(0xffffffffu, acc, 4);
        if (lane == 0) {
            float v = 2.0f * acc + Dv * u;
            float c = 0.7978845608028654f * (v + 0.044715f * v * v * v);
            float gv = v / (1.0f + __expf(-2.0f * c));
            bf16 hh, ll; split1(gv, hh, ll);
            yh[orow + (size_t)l * HDIM] = hh;
            yl[orow + (size_t)l * HDIM] = ll;
        }
    }
}

// ======================= mma.sync split-bf16 GEMM, cp.async 2-stage, 2 CTA/SM =====
#define LDSB   80
#define TILEB  (128 * LDSB)
#define STAGEB (4 * TILEB)
#define NSTAGE 2
#define GEMM_SMEM (NSTAGE * STAGEB)   // 81920 bytes -> 2 CTAs/SM

__global__ void __launch_bounds__(256, 2)
gemm_mma(const bf16* __restrict__ Ah, const bf16* __restrict__ Al,
         const bf16* __restrict__ Bh, const bf16* __restrict__ Bl,
         const float* __restrict__ bias,
         float* __restrict__ C, bf16* __restrict__ Ch, bf16* __restrict__ Cl,
         int K, int N, int mode) {
    extern __shared__ char smem[];
    uint32_t sbase = smem_u32(smem);
    int tid = threadIdx.x, wid = tid >> 5, lane = tid & 31;
    int row0 = blockIdx.y * 128, col0 = blockIdx.x * 128;
    int wm = wid >> 1, wn = wid & 1;

    float acc[2][8][4];
#pragma unroll
    for (int i = 0; i < 2; i++)
#pragma unroll
        for (int j = 0; j < 8; j++)
#pragma unroll
            for (int q = 0; q < 4; q++) acc[i][j][q] = 0.0f;

    int lr = tid >> 1;
    int lc = (tid & 1) * 16;
    const bf16* aph = Ah + (size_t)(row0 + lr) * K + lc;
    const bf16* apl = Al + (size_t)(row0 + lr) * K + lc;
    const bf16* bph = Bh + (size_t)(col0 + lr) * K + lc;
    const bf16* bpl = Bl + (size_t)(col0 + lr) * K + lc;
    uint32_t soff = (uint32_t)(lr * LDSB + lc * 2);

    int nch = K / 32;

    auto issue = [&](int c, int s) {
        uint32_t st = sbase + (uint32_t)s * STAGEB;
        int go = c * 32;
        uint32_t ah = st + soff;
        CP_ASYNC16(ah,              aph + go);
        CP_ASYNC16(ah + 16,         aph + go + 8);
        CP_ASYNC16(ah + TILEB,      apl + go);
        CP_ASYNC16(ah + TILEB + 16, apl + go + 8);
        uint32_t bh = st + 2 * TILEB + soff;
        CP_ASYNC16(bh,              bph + go);
        CP_ASYNC16(bh + 16,         bph + go + 8);
        CP_ASYNC16(bh + TILEB,      bpl + go);
        CP_ASYNC16(bh + TILEB + 16, bpl + go + 8);
    };

#pragma unroll
    for (int s = 0; s < NSTAGE - 1; ++s) {
        if (s < nch) issue(s, s);
        CP_COMMIT();
    }

    int r_lm = (lane & 7) + ((lane >> 3) & 1) * 8;
    int k_lm = ((lane >> 4) & 1) * 8;

    for (int c = 0; c < nch; ++c) {
        int cn = c + NSTAGE - 1;
        if (cn < nch) issue(cn, cn % NSTAGE);
        CP_COMMIT();
        CP_WAIT(NSTAGE - 1);
        __syncthreads();

        uint32_t st = sbase + (uint32_t)(c % NSTAGE) * STAGEB;
        uint32_t ahs = st;
        uint32_t bhs = st + 2 * TILEB;

#pragma unroll
        for (int ks = 0; ks < 2; ++ks) {
            uint32_t afh[2][4], afl[2][4], bfh[4][4], bfl[4][4];
            int kcol = ks * 16 + k_lm;
#pragma unroll
            for (int mi = 0; mi < 2; ++mi) {
                int m = wm * 32 + mi * 16 + r_lm;
                uint32_t ad = ahs + (uint32_t)(m * LDSB + kcol * 2);
                ldmatrix_x4(afh[mi], ad);
                ldmatrix_x4(afl[mi], ad + TILEB);
            }
#pragma unroll
            for (int nj = 0; nj < 4; ++nj) {
                int n = wn * 64 + nj * 16 + r_lm;
                uint32_t bd = bhs + (uint32_t)(n * LDSB + kcol * 2);
                ldmatrix_x4(bfh[nj], bd);
                ldmatrix_x4(bfl[nj], bd + TILEB);
            }
#pragma unroll
            for (int mi = 0; mi < 2; ++mi)
#pragma unroll
                for (int nj = 0; nj < 4; ++nj)
#pragma unroll
                    for (int h = 0; h < 2; ++h) {
                        float* cc = acc[mi][nj * 2 + h];
                        mma_bf16(cc, afh[mi], bfh[nj][h], bfh[nj][2 + h]);
                        mma_bf16(cc, afh[mi], bfl[nj][h], bfl[nj][2 + h]);
                        mma_bf16(cc, afl[mi], bfh[nj][h], bfh[nj][2 + h]);
                    }
        }
        __syncthreads();
    }

    int tg = lane >> 2, tq = lane & 3;
#pragma unroll
    for (int mi = 0; mi < 2; ++mi) {
        int r = row0 + wm * 32 + mi * 16 + tg;
#pragma unroll
        for (int ni = 0; ni < 8; ++ni) {
            int cix = col0 + wn * 64 + ni * 8 + tq * 2;
            float b0 = bias[cix], b1 = bias[cix + 1];
            float v0 = acc[mi][ni][0] + b0, v1 = acc[mi][ni][1] + b1;
            float v2 = acc[mi][ni][2] + b0, v3 = acc[mi][ni][3] + b1;
            if (mode == 0) {
                *(float2*)(C + (size_t)r * N + cix) = make_float2(v0, v1);
                *(float2*)(C + (size_t)(r + 8) * N + cix) = make_float2(v2, v3);
            } else {
                v0 = fmaxf(v0, 0.0f); v1 = fmaxf(v1, 0.0f);
                v2 = fmaxf(v2, 0.0f); v3 = fmaxf(v3, 0.0f);
                bf16 h0, l0, h1, l1;
                split1(v0, h0, l0); split1(v1, h1, l1);
                *(bf162*)(Ch + (size_t)r * N + cix) = bf162(h0, h1);
                *(bf162*)(Cl + (size_t)r * N + cix) = bf162(l0, l1);
                split1(v2, h0, l0); split1(v3, h1, l1);
                *(bf162*)(Ch + (size_t)(r + 8) * N + cix) = bf162(h0, h1);
                *(bf162*)(Cl + (size_t)(r + 8) * N + cix) = bf162(l0, l1);
            }
        }
    }
}

// ---------------- block reduce helper (128 threads) ------------------------------
__device__ __forceinline__ float2 block_reduce_2(float a, float b) {
    unsigned m = 0xffffffffu;
#pragma unroll
    for (int o = 16; o > 0; o >>= 1) {
        a += __shfl_down_sync(m, a, o);
        b += __shfl_down_sync(m, b, o);
    }
    __shared__ float sa[4], sb[4];
    int w = threadIdx.x >> 5, lane = threadIdx.x & 31;
    if (lane == 0) { sa[w] = a; sb[w] = b; }
    __syncthreads();
    if (threadIdx.x == 0) {
        float ta = sa[0] + sa[1] + sa[2] + sa[3];
        float tb = sb[0] + sb[1] + sb[2] + sb[3];
        sa[0] = ta; sb[0] = tb;
    }
    __syncthreads();
    return make_float2(sa[0], sb[0]);
}

// ---------------- GLU + residual + LayerNorm1 (emits bf16 hi/lo) ------------------
__global__ __launch_bounds__(128) void glu_ln_kernel(const float* __restrict__ z,
                                                     const float* __restrict__ x,
                                                     const float* __restrict__ g1,
                                                     const float* __restrict__ b1,
                                                     float* __restrict__ xln,
                                                     bf16* __restrict__ xh,
                                                     bf16* __restrict__ xl) {
    int row = blockIdx.x, tid = threadIdx.x;
    const float* zr = z + (size_t)row * (2 * HDIM);
    const float* xr = x + (size_t)row * HDIM;
    float v[4], s = 0.0f, s2 = 0.0f;
#pragma unroll
    for (int i = 0; i < 4; i++) {
        int c = tid + i * 128;
        float a = zr[c], g = zr[c + HDIM];
        float val = xr[c] + a / (1.0f + __expf(-g));
        v[i] = val; s += val; s2 += val * val;
    }
    float2 tot = block_reduce_2(s, s2);
    float mu = tot.x * (1.0f / HDIM);
    float var = tot.y * (1.0f / HDIM) - mu * mu;
    float rstd = rsqrtf(var + 1e-5f);
#pragma unroll
    for (int i = 0; i < 4; i++) {
        int c = tid + i * 128;
        float o = (v[i] - mu) * rstd * g1[c] + b1[c];
        xln[(size_t)row * HDIM + c] = o;
        bf16 hh, ll; split1(o, hh, ll);
        xh[(size_t)row * HDIM + c] = hh;
        xl[(size_t)row * HDIM + c] = ll;
    }
}

// ---------------- residual + LayerNorm2 (final output) ---------------------------
__global__ __launch_bounds__(128) void final_ln_kernel(const float* __restrict__ xln,
                                                       const float* __restrict__ y2,
                                                       const float* __restrict__ g2,
                                                       const float* __restrict__ b2,
                                                       float* __restrict__ out) {
    int row = blockIdx.x, tid = threadIdx.x;
    const float* a = xln + (size_t)row * HDIM;
    const float* b = y2 + (size_t)row * HDIM;
    float v[4], s = 0.0f, s2 = 0.0f;
#pragma unroll
    for (int i = 0; i < 4; i++) {
        int c = tid + i * 128;
        float val = a[c] + b[c];
        v[i] = val; s += val; s2 += val * val;
    }
    float2 tot = block_reduce_2(s, s2);
    float mu = tot.x * (1.0f / HDIM);
    float var = tot.y * (1.0f / HDIM) - mu * mu;
    float rstd = rsqrtf(var + 1e-5f);
#pragma unroll
    for (int i = 0; i < 4; i++) {
        int c = tid + i * 128;
        out[(size_t)row * HDIM + c] = (v[i] - mu) * rstd * g2[c] + b2[c];
    }
}

// ---------------- launch ----------------------------------------------------------
extern "C" void kernel_launch(void* const* d_in, const int* in_sizes, int n_in,
                              void* d_out, int out_size) {
    const float* x      = (const float*)d_in[0];
    const float* log_dt = (const float*)d_in[1];
    const float* A_re   = (const float*)d_in[2];
    const float* A_im   = (const float*)d_in[3];
    const float* C_re   = (const float*)d_in[4];
    const float* C_im   = (const float*)d_in[5];
    const float* D_skip = (const float*)d_in[6];
    const float* W_out  = (const float*)d_in[7];
    const float* b_out  = (const float*)d_in[8];
    const float* g1     = (const float*)d_in[9];
    const float* beta1  = (const float*)d_in[10];
    const float* g2     = (const float*)d_in[11];
    const float* beta2  = (const float*)d_in[12];
    const float* W1     = (const float*)d_in[13];
    const float* bc1    = (const float*)d_in[14];
    const float* W2     = (const float*)d_in[15];
    const float* bc2    = (const float*)d_in[16];
    float* out = (float*)d_out;

    bf16 *yh, *yl, *xh, *xl, *y1h, *y1l;
    bf16 *wouth, *woutl, *w1h, *w1l, *w2h, *w2l;
    float *z, *xln, *y2;
    cudaGetSymbolAddress((void**)&yh,  g_yh);
    cudaGetSymbolAddress((void**)&yl,  g_yl);
    cudaGetSymbolAddress((void**)&z,   g_z);
    cudaGetSymbolAddress((void**)&xln, g_xln);
    cudaGetSymbolAddress((void**)&xh,  g_xh);
    cudaGetSymbolAddress((void**)&xl,  g_xl);
    cudaGetSymbolAddress((void**)&y1h, g_y1h);
    cudaGetSymbolAddress((void**)&y1l, g_y1l);
    cudaGetSymbolAddress((void**)&y2,  g_y2);
    cudaGetSymbolAddress((void**)&wouth, g_wouth);
    cudaGetSymbolAddress((void**)&woutl, g_woutl);
    cudaGetSymbolAddress((void**)&w1h, g_w1h);
    cudaGetSymbolAddress((void**)&w1l, g_w1l);
    cudaGetSymbolAddress((void**)&w2h, g_w2h);
    cudaGetSymbolAddress((void**)&w2l, g_w2l);

    cudaFuncSetAttribute(gemm_mma, cudaFuncAttributeMaxDynamicSharedMemorySize, GEMM_SMEM);

    // 1) discretize SSM params (+ w^SEGT)
    precompute_kernel<<<HDIM, NST>>>(log_dt, A_re, A_im, C_re, C_im);

    // 2) chunked scan: pass1 (segment end states)
    scan_part1<<<(BSZ * HDIM * (SEG - 1)) / 32, 256>>>(x);

    // 3) combine carries
    scan_combine<<<(BSZ * HDIM * NST) / 256, 256>>>();

    // 4) pass2: full recurrence + gelu + bf16 split (profiled slot)
    scan_part2<<<(BSZ * HDIM * SEG) / 32, 256>>>(x, D_skip, yh, yl);

    // 5) split all weights
    split_all_kernel<<<(4 * HDIM * HDIM + 255) / 256, 256>>>(W_out, W1, W2);

    // 6) GLU projection
    gemm_mma<<<dim3((2 * HDIM) / 128, ROWS / 128), 256, GEMM_SMEM>>>(
        yh, yl, wouth, woutl, b_out, z, nullptr, nullptr, HDIM, 2 * HDIM, 0);

    // 7) GLU + residual + LN1
    glu_ln_kernel<<<ROWS, 128>>>(z, x, g1, beta1, xln, xh, xl);

    // 8) FFN: y1 = relu(xln @ W1^T + bc1)
    gemm_mma<<<dim3(HDIM / 128, ROWS / 128), 256, GEMM_SMEM>>>(
        xh, xl, w1h, w1l, bc1, nullptr, y1h, y1l, HDIM, HDIM, 1);

    // 9) y2 = y1 @ W2^T + bc2
    gemm_mma<<<dim3(HDIM / 128, ROWS / 128), 256, GEMM_SMEM>>>(
        y1h, y1l, w2h, w2l, bc2, y2, nullptr, nullptr, HDIM, HDIM, 0);

    // 10) out = LN2(xln + y2)
    final_ln_kernel<<<ROWS, 128>>>(xln, y2, g2, beta2, out);
}

// round 7
// speedup vs baseline: 3.1170x; 1.2422x over previous
#include <cuda_runtime.h>
#include <cuda_bf16.h>
#include <math.h>
#include <stdint.h>

#define BSZ   8
#define LSEQ  2048
#define HDIM  512
#define NST   64
#define ROWS  (BSZ*LSEQ)      // 16384
#define SEG   16
#define SEGT  (LSEQ/SEG)      // 128

typedef __nv_bfloat16 bf16;
typedef __nv_bfloat162 bf162;

// ---------------- scratch ----------------------------------------------------------
__device__ float g_wre[HDIM*NST];
__device__ float g_wim[HDIM*NST];
__device__ float g_wTre[HDIM*NST];
__device__ float g_wTim[HDIM*NST];
__device__ float g_ctre[HDIM*NST];
__device__ float g_ctim[HDIM*NST];

__device__ float g_sendre[(size_t)BSZ*HDIM*SEG*NST];
__device__ float g_sendim[(size_t)BSZ*HDIM*SEG*NST];
__device__ float g_carre [(size_t)BSZ*HDIM*SEG*NST];
__device__ float g_carim [(size_t)BSZ*HDIM*SEG*NST];

__device__ bf16  g_yh [(size_t)ROWS*HDIM];
__device__ bf16  g_yl [(size_t)ROWS*HDIM];
__device__ float g_z  [(size_t)ROWS*2*HDIM];
__device__ float g_xln[(size_t)ROWS*HDIM];
__device__ bf16  g_xh [(size_t)ROWS*HDIM];
__device__ bf16  g_xl [(size_t)ROWS*HDIM];
__device__ bf16  g_y1h[(size_t)ROWS*HDIM];
__device__ bf16  g_y1l[(size_t)ROWS*HDIM];
__device__ float g_y2 [(size_t)ROWS*HDIM];

__device__ bf16 g_wouth[2*HDIM*HDIM];
__device__ bf16 g_woutl[2*HDIM*HDIM];
__device__ bf16 g_w1h[HDIM*HDIM];
__device__ bf16 g_w1l[HDIM*HDIM];
__device__ bf16 g_w2h[HDIM*HDIM];
__device__ bf16 g_w2l[HDIM*HDIM];

// =============================== helpers =========================================
__device__ __forceinline__ uint32_t smem_u32(const void* p) {
    uint32_t a;
    asm("{ .reg .u64 t; cvta.to.shared.u64 t, %1; cvt.u32.u64 %0, t; }" : "=r"(a) : "l"(p));
    return a;
}

__device__ __forceinline__ void ldmatrix_x4(uint32_t* r, uint32_t addr) {
    asm volatile("ldmatrix.sync.aligned.m8n8.x4.shared.b16 {%0,%1,%2,%3}, [%4];"
        : "=r"(r[0]), "=r"(r[1]), "=r"(r[2]), "=r"(r[3]) : "r"(addr));
}

__device__ __forceinline__ void mma_bf16(float* c, const uint32_t* a,
                                         uint32_t b0, uint32_t b1) {
    asm volatile("mma.sync.aligned.m16n8k16.row.col.f32.bf16.bf16.f32 "
        "{%0,%1,%2,%3}, {%4,%5,%6,%7}, {%8,%9}, {%0,%1,%2,%3};"
        : "+f"(c[0]), "+f"(c[1]), "+f"(c[2]), "+f"(c[3])
        : "r"(a[0]), "r"(a[1]), "r"(a[2]), "r"(a[3]), "r"(b0), "r"(b1));
}

#define CP_ASYNC16(saddr, gaddr) \
    asm volatile("cp.async.cg.shared.global [%0], [%1], 16;" \
                 :: "r"(saddr), "l"(gaddr) : "memory")
#define CP_COMMIT() asm volatile("cp.async.commit_group;" ::: "memory")
#define CP_WAIT(n)  asm volatile("cp.async.wait_group %0;" :: "n"(n) : "memory")

__device__ __forceinline__ void split1(float v, bf16& h, bf16& l) {
    h = __float2bfloat16(v);
    l = __float2bfloat16(v - __bfloat162float(h));
}

// ---- packed f32x2 ops (Blackwell) ----
__device__ __forceinline__ uint64_t pk2(float lo, float hi) {
    uint64_t r; asm("mov.b64 %0, {%1,%2};" : "=l"(r) : "f"(lo), "f"(hi)); return r;
}
__device__ __forceinline__ void upk2(uint64_t v, float& lo, float& hi) {
    asm("mov.b64 {%0,%1}, %2;" : "=f"(lo), "=f"(hi) : "l"(v));
}
__device__ __forceinline__ uint64_t fma2(uint64_t a, uint64_t b, uint64_t c) {
    uint64_t d; asm("fma.rn.f32x2 %0, %1, %2, %3;" : "=l"(d) : "l"(a), "l"(b), "l"(c)); return d;
}
__device__ __forceinline__ uint64_t mul2(uint64_t a, uint64_t b) {
    uint64_t d; asm("mul.rn.f32x2 %0, %1, %2;" : "=l"(d) : "l"(a), "l"(b)); return d;
}
__device__ __forceinline__ uint64_t add2(uint64_t a, uint64_t b) {
    uint64_t d; asm("add.rn.f32x2 %0, %1, %2;" : "=l"(d) : "l"(a), "l"(b)); return d;
}

// ---------------- weight split -----------------------------------------------------
__global__ void split_all_kernel(const float* __restrict__ wout,
                                 const float* __restrict__ w1,
                                 const float* __restrict__ w2) {
    int i = blockIdx.x * blockDim.x + threadIdx.x;
    const int n1 = 2 * HDIM * HDIM;
    const int n2 = HDIM * HDIM;
    if (i < n1) {
        bf16 h, l; split1(wout[i], h, l);
        g_wouth[i] = h; g_woutl[i] = l;
    } else if (i < n1 + n2) {
        int j = i - n1;
        bf16 h, l; split1(w1[j], h, l);
        g_w1h[j] = h; g_w1l[j] = l;
    } else {
        int j = i - n1 - n2;
        bf16 h, l; split1(w2[j], h, l);
        g_w2h[j] = h; g_w2l[j] = l;
    }
}

// ---------------- precompute -------------------------------------------------------
__global__ void precompute_kernel(const float* __restrict__ log_dt,
                                  const float* __restrict__ Are,
                                  const float* __restrict__ Aim,
                                  const float* __restrict__ Cre,
                                  const float* __restrict__ Cim) {
    int h = blockIdx.x, n = threadIdx.x;
    int idx = h * NST + n;
    float dt = expf(log_dt[h]);
    float ar = Are[idx] * dt;
    float ai = Aim[idx] * dt;
    float e  = expf(ar);
    float sb, cb;
    sincosf(ai, &sb, &cb);
    float wre = e * cb, wim = e * sb;
    float eT = expf(ar * (float)SEGT);
    float sT, cT;
    sincosf(ai * (float)SEGT, &sT, &cT);
    g_wTre[idx] = eT * cT;
    g_wTim[idx] = eT * sT;

    float Ere = wre - 1.0f, Eim = wim;
    float Ar = Are[idx], Ai = Aim[idx];
    float inv = 1.0f / (Ar * Ar + Ai * Ai);
    float rre = (Ere * Ar + Eim * Ai) * inv;
    float rim = (Eim * Ar - Ere * Ai) * inv;
    float cr = Cre[idx], ci = Cim[idx];
    g_ctre[idx] = cr * rre - ci * rim;
    g_ctim[idx] = cr * rim + ci * rre;
    g_wre[idx]  = wre;
    g_wim[idx]  = wim;
}

// ---------------- scan pass 1 (f32x2 packed) ---------------------------------------
__global__ __launch_bounds__(256) void scan_part1(const float* __restrict__ x) {
    int tid  = threadIdx.x;
    int gid  = blockIdx.x * 32 + (tid >> 3);
    int lane = tid & 7;
    int seg  = gid % (SEG - 1);
    int rem  = gid / (SEG - 1);
    int h = rem & (HDIM - 1);
    int b = rem >> 9;

    uint64_t wre01[4], wim01[4], nwim01[4], sre01[4], sim01[4];
    int base = h * NST + lane * 8;
#pragma unroll
    for (int p = 0; p < 4; p++) {
        float w0 = g_wre[base + 2*p], w1 = g_wre[base + 2*p + 1];
        float i0 = g_wim[base + 2*p], i1 = g_wim[base + 2*p + 1];
        wre01[p]  = pk2(w0, w1);
        wim01[p]  = pk2(i0, i1);
        nwim01[p] = pk2(-i0, -i1);
        sre01[p] = 0; sim01[p] = 0;
    }
    const float* xp = x + ((size_t)b * LSEQ + seg * SEGT) * HDIM + h;

    // distributed u: lane holds u[l0+lane]
    float ucur = __ldg(xp + (size_t)lane * HDIM);
    for (int l0 = 0; l0 < SEGT; l0 += 8) {
        int ln = l0 + 8 + lane; if (ln > SEGT - 1) ln = SEGT - 1;
        float unext = __ldg(xp + (size_t)ln * HDIM);
#pragma unroll
        for (int k = 0; k < 8; k++) {
            float u = __shfl_sync(0xffffffffu, ucur, k, 8);
            uint64_t u2 = pk2(u, u);
#pragma unroll
            for (int p = 0; p < 4; p++) {
                uint64_t nr = fma2(wre01[p], sre01[p], fma2(nwim01[p], sim01[p], u2));
                uint64_t ni = fma2(wim01[p], sre01[p], mul2(wre01[p], sim01[p]));
                sre01[p] = nr; sim01[p] = ni;
            }
        }
        ucur = unext;
    }

    size_t ob = (((size_t)(b * HDIM + h) * SEG) + seg) * NST + lane * 8;
#pragma unroll
    for (int p = 0; p < 4; p++) {
        float r0, r1, i0, i1;
        upk2(sre01[p], r0, r1);
        upk2(sim01[p], i0, i1);
        g_sendre[ob + 2*p] = r0; g_sendre[ob + 2*p + 1] = r1;
        g_sendim[ob + 2*p] = i0; g_sendim[ob + 2*p + 1] = i1;
    }
}

// ---------------- combine ----------------------------------------------------------
__global__ __launch_bounds__(256) void scan_combine() {
    int idx = blockIdx.x * blockDim.x + threadIdx.x;
    int n = idx & (NST - 1);
    int rem = idx >> 6;
    int h = rem & (HDIM - 1);
    int b = rem >> 9;
    float wTre = g_wTre[h * NST + n];
    float wTim = g_wTim[h * NST + n];
    float cr = 0.0f, ci = 0.0f;
    size_t base = ((size_t)(b * HDIM + h) * SEG) * NST + n;
#pragma unroll
    for (int j = 0; j < SEG; j++) {
        g_carre[base + (size_t)j * NST] = cr;
        g_carim[base + (size_t)j * NST] = ci;
        if (j < SEG - 1) {
            float er = g_sendre[base + (size_t)j * NST];
            float ei = g_sendim[base + (size_t)j * NST];
            float nr = fmaf(wTre, cr, fmaf(-wTim, ci, er));
            float ni = fmaf(wTim, cr, fmaf(wTre, ci, ei));
            cr = nr; ci = ni;
        }
    }
}

// ---------------- scan pass 2 (f32x2 packed + batched output) ----------------------
__global__ __launch_bounds__(256) void scan_part2(const float* __restrict__ x,
                                                  const float* __restrict__ Dskip,
                                                  bf16* __restrict__ yh,
                                                  bf16* __restrict__ yl) {
    int tid  = threadIdx.x;
    int gid  = blockIdx.x * 32 + (tid >> 3);
    int lane = tid & 7;
    int seg  = gid & (SEG - 1);
    int rem  = gid >> 4;
    int h = rem & (HDIM - 1);
    int b = rem >> 9;

    uint64_t wre01[4], wim01[4], nwim01[4], cre01[4], ncim01[4], sre01[4], sim01[4];
    int base = h * NST + lane * 8;
    size_t cb = (((size_t)(b * HDIM + h) * SEG) + seg) * NST + lane * 8;
#pragma unroll
    for (int p = 0; p < 4; p++) {
        float w0 = g_wre[base + 2*p], w1 = g_wre[base + 2*p + 1];
        float i0 = g_wim[base + 2*p], i1 = g_wim[base + 2*p + 1];
        float c0 = g_ctre[base + 2*p], c1 = g_ctre[base + 2*p + 1];
        float d0 = g_ctim[base + 2*p], d1 = g_ctim[base + 2*p + 1];
        wre01[p]  = pk2(w0, w1);
        wim01[p]  = pk2(i0, i1);
        nwim01[p] = pk2(-i0, -i1);
        cre01[p]  = pk2(c0, c1);
        ncim01[p] = pk2(-d0, -d1);
        sre01[p] = pk2(g_carre[cb + 2*p], g_carre[cb + 2*p + 1]);
        sim01[p] = pk2(g_carim[cb + 2*p], g_carim[cb + 2*p + 1]);
    }
    float Dv = Dskip[h];
    const float* xp = x + ((size_t)b * LSEQ + seg * SEGT) * HDIM + h;
    size_t orow = ((size_t)b * LSEQ + seg * SEGT) * HDIM + h;

    float ucur = __ldg(xp + (size_t)lane * HDIM);
    for (int l0 = 0; l0 < SEGT; l0 += 8) {
        int ln = l0 + 8 + lane; if (ln > SEGT - 1) ln = SEGT - 1;
        float unext = __ldg(xp + (size_t)ln * HDIM);
        float vmine = 0.0f;
#pragma unroll
        for (int k = 0; k < 8; k++) {
            float u = __shfl_sync(0xffffffffu, ucur, k, 8);
            uint64_t u2 = pk2(u, u);
            uint64_t accR, accI;
            {
                uint64_t nr = fma2(wre01[0], sre01[0], fma2(nwim01[0], sim01[0], u2));
                uint64_t ni = fma2(wim01[0], sre01[0], mul2(wre01[0], sim01[0]));
                sre01[0] = nr; sim01[0] = ni;
                accR = mul2(cre01[0], nr);
                accI = mul2(ncim01[0], ni);
            }
#pragma unroll
            for (int p = 1; p < 4; p++) {
                uint64_t nr = fma2(wre01[p], sre01[p], fma2(nwim01[p], sim01[p], u2));
                uint64_t ni = fma2(wim01[p], sre01[p], mul2(wre01[p], sim01[p]));
                sre01[p] = nr; sim01[p] = ni;
                accR = fma2(cre01[p], nr, accR);
                accI = fma2(ncim01[p], ni, accI);
            }
            uint64_t t = add2(accR, accI);
            float ta, tb; upk2(t, ta, tb);
            float acc = ta + tb;
            acc += __shfl_xor_sync(0xffffffffu, acc, 1);
            acc += __shfl_xor_sync(0xffffffffu, acc, 2);
            acc += __shfl_xor_sync(0xffffffffu, acc, 4);
            float v = fmaf(2.0f, acc, Dv * u);
            if (lane == k) vmine = v;
        }
        // each lane outputs step l0+lane
        {
            float vv = vmine;
            float c = 0.7978845608028654f * (vv + 0.044715f * vv * vv * vv);
            float gv = vv / (1.0f + __expf(-2.0f * c));
            bf16 hh, ll; split1(gv, hh, ll);
            size_t o = orow + (size_t)(l0 + lane) * HDIM;
            yh[o] = hh;
            yl[o] = ll;
        }
        ucur = unext;
    }
}

// ======================= mma.sync split-bf16 GEMM, cp.async 2-stage, 2 CTA/SM =====
#define LDSB   80
#define TILEB  (128 * LDSB)
#define STAGEB (4 * TILEB)
#define NSTAGE 2
#define GEMM_SMEM (NSTAGE * STAGEB)   // 81920 bytes -> 2 CTAs/SM

__global__ void __launch_bounds__(256, 2)
gemm_mma(const bf16* __restrict__ Ah, const bf16* __restrict__ Al,
         const bf16* __restrict__ Bh, const bf16* __restrict__ Bl,
         const float* __restrict__ bias,
         float* __restrict__ C, bf16* __restrict__ Ch, bf16* __restrict__ Cl,
         int K, int N, int mode) {
    extern __shared__ char smem[];
    uint32_t sbase = smem_u32(smem);
    int tid = threadIdx.x, wid = tid >> 5, lane = tid & 31;
    int row0 = blockIdx.y * 128, col0 = blockIdx.x * 128;
    int wm = wid >> 1, wn = wid & 1;

    float acc[2][8][4];
#pragma unroll
    for (int i = 0; i < 2; i++)
#pragma unroll
        for (int j = 0; j < 8; j++)
#pragma unroll
            for (int q = 0; q < 4; q++) acc[i][j][q] = 0.0f;

    int lr = tid >> 1;
    int lc = (tid & 1) * 16;
    const bf16* aph = Ah + (size_t)(row0 + lr) * K + lc;
    const bf16* apl = Al + (size_t)(row0 + lr) * K + lc;
    const bf16* bph = Bh + (size_t)(col0 + lr) * K + lc;
    const bf16* bpl = Bl + (size_t)(col0 + lr) * K + lc;
    uint32_t soff = (uint32_t)(lr * LDSB + lc * 2);

    int nch = K / 32;

    auto issue = [&](int c, int s) {
        uint32_t st = sbase + (uint32_t)s * STAGEB;
        int go = c * 32;
        uint32_t ah = st + soff;
        CP_ASYNC16(ah,              aph + go);
        CP_ASYNC16(ah + 16,         aph + go + 8);
        CP_ASYNC16(ah + TILEB,      apl + go);
        CP_ASYNC16(ah + TILEB + 16, apl + go + 8);
        uint32_t bh = st + 2 * TILEB + soff;
        CP_ASYNC16(bh,              bph + go);
        CP_ASYNC16(bh + 16,         bph + go + 8);
        CP_ASYNC16(bh + TILEB,      bpl + go);
        CP_ASYNC16(bh + TILEB + 16, bpl + go + 8);
    };

#pragma unroll
    for (int s = 0; s < NSTAGE - 1; ++s) {
        if (s < nch) issue(s, s);
        CP_COMMIT();
    }

    int r_lm = (lane & 7) + ((lane >> 3) & 1) * 8;
    int k_lm = ((lane >> 4) & 1) * 8;

    for (int c = 0; c < nch; ++c) {
        int cn = c + NSTAGE - 1;
        if (cn < nch) issue(cn, cn % NSTAGE);
        CP_COMMIT();
        CP_WAIT(NSTAGE - 1);
        __syncthreads();

        uint32_t st = sbase + (uint32_t)(c % NSTAGE) * STAGEB;
        uint32_t ahs = st;
        uint32_t bhs = st + 2 * TILEB;

#pragma unroll
        for (int ks = 0; ks < 2; ++ks) {
            int kcol = ks * 16 + k_lm;
            uint32_t afh[2][4], afl[2][4];
#pragma unroll
            for (int mi = 0; mi < 2; ++mi) {
                int m = wm * 32 + mi * 16 + r_lm;
                uint32_t ad = ahs + (uint32_t)(m * LDSB + kcol * 2);
                ldmatrix_x4(afh[mi], ad);
                ldmatrix_x4(afl[mi], ad + TILEB);
            }
            // interleave B-frag loads with their MMAs to cut live registers
#pragma unroll
            for (int nj = 0; nj < 4; ++nj) {
                uint32_t bfh[4], bfl[4];
                int n = wn * 64 + nj * 16 + r_lm;
                uint32_t bd = bhs + (uint32_t)(n * LDSB + kcol * 2);
                ldmatrix_x4(bfh, bd);
                ldmatrix_x4(bfl, bd + TILEB);
#pragma unroll
                for (int mi = 0; mi < 2; ++mi)
#pragma unroll
                    for (int h = 0; h < 2; ++h) {
                        float* cc = acc[mi][nj * 2 + h];
                        mma_bf16(cc, afh[mi], bfh[h], bfh[2 + h]);
                        mma_bf16(cc, afh[mi], bfl[h], bfl[2 + h]);
                        mma_bf16(cc, afl[mi], bfh[h], bfh[2 + h]);
                    }
            }
        }
        __syncthreads();
    }

    int tg = lane >> 2, tq = lane & 3;
#pragma unroll
    for (int mi = 0; mi < 2; ++mi) {
        int r = row0 + wm * 32 + mi * 16 + tg;
#pragma unroll
        for (int ni = 0; ni < 8; ++ni) {
            int cix = col0 + wn * 64 + ni * 8 + tq * 2;
            float b0 = bias[cix], b1 = bias[cix + 1];
            float v0 = acc[mi][ni][0] + b0, v1 = acc[mi][ni][1] + b1;
            float v2 = acc[mi][ni][2] + b0, v3 = acc[mi][ni][3] + b1;
            if (mode == 0) {
                *(float2*)(C + (size_t)r * N + cix) = make_float2(v0, v1);
                *(float2*)(C + (size_t)(r + 8) * N + cix) = make_float2(v2, v3);
            } else {
                v0 = fmaxf(v0, 0.0f); v1 = fmaxf(v1, 0.0f);
                v2 = fmaxf(v2, 0.0f); v3 = fmaxf(v3, 0.0f);
                bf16 h0, l0, h1, l1;
                split1(v0, h0, l0); split1(v1, h1, l1);
                *(bf162*)(Ch + (size_t)r * N + cix) = bf162(h0, h1);
                *(bf162*)(Cl + (size_t)r * N + cix) = bf162(l0, l1);
                split1(v2, h0, l0); split1(v3, h1, l1);
                *(bf162*)(Ch + (size_t)(r + 8) * N + cix) = bf162(h0, h1);
                *(bf162*)(Cl + (size_t)(r + 8) * N + cix) = bf162(l0, l1);
            }
        }
    }
}

// ---------------- block reduce helper ---------------------------------------------
__device__ __forceinline__ float2 block_reduce_2(float a, float b) {
    unsigned m = 0xffffffffu;
#pragma unroll
    for (int o = 16; o > 0; o >>= 1) {
        a += __shfl_down_sync(m, a, o);
        b += __shfl_down_sync(m, b, o);
    }
    __shared__ float sa[4], sb[4];
    int w = threadIdx.x >> 5, lane = threadIdx.x & 31;
    if (lane == 0) { sa[w] = a; sb[w] = b; }
    __syncthreads();
    if (threadIdx.x == 0) {
        float ta = sa[0] + sa[1] + sa[2] + sa[3];
        float tb = sb[0] + sb[1] + sb[2] + sb[3];
        sa[0] = ta; sb[0] = tb;
    }
    __syncthreads();
    return make_float2(sa[0], sb[0]);
}

// ---------------- GLU + residual + LN1 ---------------------------------------------
__global__ __launch_bounds__(128) void glu_ln_kernel(const float* __restrict__ z,
                                                     const float* __restrict__ x,
                                                     const float* __restrict__ g1,
                                                     const float* __restrict__ b1,
                                                     float* __restrict__ xln,
                                                     bf16* __restrict__ xh,
                                                     bf16* __restrict__ xl) {
    int row = blockIdx.x, tid = threadIdx.x;
    const float* zr = z + (size_t)row * (2 * HDIM);
    const float* xr = x + (size_t)row * HDIM;
    float v[4], s = 0.0f, s2 = 0.0f;
#pragma unroll
    for (int i = 0; i < 4; i++) {
        int c = tid + i * 128;
        float a = zr[c], g = zr[c + HDIM];
        float val = xr[c] + a / (1.0f + __expf(-g));
        v[i] = val; s += val; s2 += val * val;
    }
    float2 tot = block_reduce_2(s, s2);
    float mu = tot.x * (1.0f / HDIM);
    float var = tot.y * (1.0f / HDIM) - mu * mu;
    float rstd = rsqrtf(var + 1e-5f);
#pragma unroll
    for (int i = 0; i < 4; i++) {
        int c = tid + i * 128;
        float o = (v[i] - mu) * rstd * g1[c] + b1[c];
        xln[(size_t)row * HDIM + c] = o;
        bf16 hh, ll; split1(o, hh, ll);
        xh[(size_t)row * HDIM + c] = hh;
        xl[(size_t)row * HDIM + c] = ll;
    }
}

// ---------------- residual + LN2 ---------------------------------------------------
__global__ __launch_bounds__(128) void final_ln_kernel(const float* __restrict__ xln,
                                                       const float* __restrict__ y2,
                                                       const float* __restrict__ g2,
                                                       const float* __restrict__ b2,
                                                       float* __restrict__ out) {
    int row = blockIdx.x, tid = threadIdx.x;
    const float* a = xln + (size_t)row * HDIM;
    const float* b = y2 + (size_t)row * HDIM;
    float v[4], s = 0.0f, s2 = 0.0f;
#pragma unroll
    for (int i = 0; i < 4; i++) {
        int c = tid + i * 128;
        float val = a[c] + b[c];
        v[i] = val; s += val; s2 += val * val;
    }
    float2 tot = block_reduce_2(s, s2);
    float mu = tot.x * (1.0f / HDIM);
    float var = tot.y * (1.0f / HDIM) - mu * mu;
    float rstd = rsqrtf(var + 1e-5f);
#pragma unroll
    for (int i = 0; i < 4; i++) {
        int c = tid + i * 128;
        out[(size_t)row * HDIM + c] = (v[i] - mu) * rstd * g2[c] + b2[c];
    }
}

// ---------------- launch ------------------------------------------------------------
extern "C" void kernel_launch(void* const* d_in, const int* in_sizes, int n_in,
                              void* d_out, int out_size) {
    const float* x      = (const float*)d_in[0];
    const float* log_dt = (const float*)d_in[1];
    const float* A_re   = (const float*)d_in[2];
    const float* A_im   = (const float*)d_in[3];
    const float* C_re   = (const float*)d_in[4];
    const float* C_im   = (const float*)d_in[5];
    const float* D_skip = (const float*)d_in[6];
    const float* W_out  = (const float*)d_in[7];
    const float* b_out  = (const float*)d_in[8];
    const float* g1     = (const float*)d_in[9];
    const float* beta1  = (const float*)d_in[10];
    const float* g2     = (const float*)d_in[11];
    const float* beta2  = (const float*)d_in[12];
    const float* W1     = (const float*)d_in[13];
    const float* bc1    = (const float*)d_in[14];
    const float* W2     = (const float*)d_in[15];
    const float* bc2    = (const float*)d_in[16];
    float* out = (float*)d_out;

    bf16 *yh, *yl, *xh, *xl, *y1h, *y1l;
    bf16 *wouth, *woutl, *w1h, *w1l, *w2h, *w2l;
    float *z, *xln, *y2;
    cudaGetSymbolAddress((void**)&yh,  g_yh);
    cudaGetSymbolAddress((void**)&yl,  g_yl);
    cudaGetSymbolAddress((void**)&z,   g_z);
    cudaGetSymbolAddress((void**)&xln, g_xln);
    cudaGetSymbolAddress((void**)&xh,  g_xh);
    cudaGetSymbolAddress((void**)&xl,  g_xl);
    cudaGetSymbolAddress((void**)&y1h, g_y1h);
    cudaGetSymbolAddress((void**)&y1l, g_y1l);
    cudaGetSymbolAddress((void**)&y2,  g_y2);
    cudaGetSymbolAddress((void**)&wouth, g_wouth);
    cudaGetSymbolAddress((void**)&woutl, g_woutl);
    cudaGetSymbolAddress((void**)&w1h, g_w1h);
    cudaGetSymbolAddress((void**)&w1l, g_w1l);
    cudaGetSymbolAddress((void**)&w2h, g_w2h);
    cudaGetSymbolAddress((void**)&w2l, g_w2l);

    cudaFuncSetAttribute(gemm_mma, cudaFuncAttributeMaxDynamicSharedMemorySize, GEMM_SMEM);

    precompute_kernel<<<HDIM, NST>>>(log_dt, A_re, A_im, C_re, C_im);

    scan_part1<<<(BSZ * HDIM * (SEG - 1)) / 32, 256>>>(x);
    scan_combine<<<(BSZ * HDIM * NST) / 256, 256>>>();

    // profiled slot (#4): pass2
    scan_part2<<<(BSZ * HDIM * SEG) / 32, 256>>>(x, D_skip, yh, yl);

    split_all_kernel<<<(4 * HDIM * HDIM + 255) / 256, 256>>>(W_out, W1, W2);

    gemm_mma<<<dim3((2 * HDIM) / 128, ROWS / 128), 256, GEMM_SMEM>>>(
        yh, yl, wouth, woutl, b_out, z, nullptr, nullptr, HDIM, 2 * HDIM, 0);

    glu_ln_kernel<<<ROWS, 128>>>(z, x, g1, beta1, xln, xh, xl);

    gemm_mma<<<dim3(HDIM / 128, ROWS / 128), 256, GEMM_SMEM>>>(
        xh, xl, w1h, w1l, bc1, nullptr, y1h, y1l, HDIM, HDIM, 1);

    gemm_mma<<<dim3(HDIM / 128, ROWS / 128), 256, GEMM_SMEM>>>(
        y1h, y1l, w2h, w2l, bc2, y2, nullptr, nullptr, HDIM, HDIM, 0);

    final_ln_kernel<<<ROWS, 128>>>(xln, y2, g2, beta2, out);
}

// round 8
// speedup vs baseline: 3.2198x; 1.0330x over previous
#include <cuda_runtime.h>
#include <cuda_bf16.h>
#include <math.h>
#include <stdint.h>

#define BSZ   8
#define LSEQ  2048
#define HDIM  512
#define NST   64
#define ROWS  (BSZ*LSEQ)      // 16384
#define SEG   16
#define SEGT  (LSEQ/SEG)      // 128

typedef __nv_bfloat16 bf16;
typedef __nv_bfloat162 bf162;

// ---------------- scratch ----------------------------------------------------------
__device__ float g_wre[HDIM*NST];
__device__ float g_wim[HDIM*NST];
__device__ float g_wTre[HDIM*NST];
__device__ float g_wTim[HDIM*NST];
__device__ float g_ctre[HDIM*NST];
__device__ float g_ctim[HDIM*NST];

__device__ float g_sendre[(size_t)BSZ*HDIM*SEG*NST];
__device__ float g_sendim[(size_t)BSZ*HDIM*SEG*NST];
__device__ float g_carre [(size_t)BSZ*HDIM*SEG*NST];
__device__ float g_carim [(size_t)BSZ*HDIM*SEG*NST];

__device__ bf16  g_yh [(size_t)ROWS*HDIM];
__device__ bf16  g_yl [(size_t)ROWS*HDIM];
__device__ float g_z  [(size_t)ROWS*2*HDIM];
__device__ float g_xln[(size_t)ROWS*HDIM];
__device__ bf16  g_xh [(size_t)ROWS*HDIM];
__device__ bf16  g_xl [(size_t)ROWS*HDIM];
__device__ bf16  g_y1h[(size_t)ROWS*HDIM];
__device__ bf16  g_y1l[(size_t)ROWS*HDIM];
__device__ float g_y2 [(size_t)ROWS*HDIM];

__device__ bf16 g_wouth[2*HDIM*HDIM];
__device__ bf16 g_woutl[2*HDIM*HDIM];
__device__ bf16 g_w1h[HDIM*HDIM];
__device__ bf16 g_w1l[HDIM*HDIM];
__device__ bf16 g_w2h[HDIM*HDIM];
__device__ bf16 g_w2l[HDIM*HDIM];

// =============================== helpers =========================================
__device__ __forceinline__ uint32_t smem_u32(const void* p) {
    uint32_t a;
    asm("{ .reg .u64 t; cvta.to.shared.u64 t, %1; cvt.u32.u64 %0, t; }" : "=r"(a) : "l"(p));
    return a;
}

__device__ __forceinline__ void ldmatrix_x4(uint32_t* r, uint32_t addr) {
    asm volatile("ldmatrix.sync.aligned.m8n8.x4.shared.b16 {%0,%1,%2,%3}, [%4];"
        : "=r"(r[0]), "=r"(r[1]), "=r"(r[2]), "=r"(r[3]) : "r"(addr));
}

__device__ __forceinline__ void mma_bf16(float* c, const uint32_t* a,
                                         uint32_t b0, uint32_t b1) {
    asm volatile("mma.sync.aligned.m16n8k16.row.col.f32.bf16.bf16.f32 "
        "{%0,%1,%2,%3}, {%4,%5,%6,%7}, {%8,%9}, {%0,%1,%2,%3};"
        : "+f"(c[0]), "+f"(c[1]), "+f"(c[2]), "+f"(c[3])
        : "r"(a[0]), "r"(a[1]), "r"(a[2]), "r"(a[3]), "r"(b0), "r"(b1));
}

#define CP_ASYNC16(saddr, gaddr) \
    asm volatile("cp.async.cg.shared.global [%0], [%1], 16;" \
                 :: "r"(saddr), "l"(gaddr) : "memory")
#define CP_COMMIT() asm volatile("cp.async.commit_group;" ::: "memory")
#define CP_WAIT(n)  asm volatile("cp.async.wait_group %0;" :: "n"(n) : "memory")

__device__ __forceinline__ void split1(float v, bf16& h, bf16& l) {
    h = __float2bfloat16(v);
    l = __float2bfloat16(v - __bfloat162float(h));
}

// ---- packed f32x2 ops (Blackwell) ----
__device__ __forceinline__ uint64_t pk2(float lo, float hi) {
    uint64_t r; asm("mov.b64 %0, {%1,%2};" : "=l"(r) : "f"(lo), "f"(hi)); return r;
}
__device__ __forceinline__ void upk2(uint64_t v, float& lo, float& hi) {
    asm("mov.b64 {%0,%1}, %2;" : "=f"(lo), "=f"(hi) : "l"(v));
}
__device__ __forceinline__ uint64_t fma2(uint64_t a, uint64_t b, uint64_t c) {
    uint64_t d; asm("fma.rn.f32x2 %0, %1, %2, %3;" : "=l"(d) : "l"(a), "l"(b), "l"(c)); return d;
}
__device__ __forceinline__ uint64_t mul2(uint64_t a, uint64_t b) {
    uint64_t d; asm("mul.rn.f32x2 %0, %1, %2;" : "=l"(d) : "l"(a), "l"(b)); return d;
}
__device__ __forceinline__ uint64_t add2(uint64_t a, uint64_t b) {
    uint64_t d; asm("add.rn.f32x2 %0, %1, %2;" : "=l"(d) : "l"(a), "l"(b)); return d;
}

// ---------------- weight split -----------------------------------------------------
__global__ void split_all_kernel(const float* __restrict__ wout,
                                 const float* __restrict__ w1,
                                 const float* __restrict__ w2) {
    int i = blockIdx.x * blockDim.x + threadIdx.x;
    const int n1 = 2 * HDIM * HDIM;
    const int n2 = HDIM * HDIM;
    if (i < n1) {
        bf16 h, l; split1(wout[i], h, l);
        g_wouth[i] = h; g_woutl[i] = l;
    } else if (i < n1 + n2) {
        int j = i - n1;
        bf16 h, l; split1(w1[j], h, l);
        g_w1h[j] = h; g_w1l[j] = l;
    } else {
        int j = i - n1 - n2;
        bf16 h, l; split1(w2[j], h, l);
        g_w2h[j] = h; g_w2l[j] = l;
    }
}

// ---------------- precompute -------------------------------------------------------
__global__ void precompute_kernel(const float* __restrict__ log_dt,
                                  const float* __restrict__ Are,
                                  const float* __restrict__ Aim,
                                  const float* __restrict__ Cre,
                                  const float* __restrict__ Cim) {
    int h = blockIdx.x, n = threadIdx.x;
    int idx = h * NST + n;
    float dt = expf(log_dt[h]);
    float ar = Are[idx] * dt;
    float ai = Aim[idx] * dt;
    float e  = expf(ar);
    float sb, cb;
    sincosf(ai, &sb, &cb);
    float wre = e * cb, wim = e * sb;
    float eT = expf(ar * (float)SEGT);
    float sT, cT;
    sincosf(ai * (float)SEGT, &sT, &cT);
    g_wTre[idx] = eT * cT;
    g_wTim[idx] = eT * sT;

    float Ere = wre - 1.0f, Eim = wim;
    float Ar = Are[idx], Ai = Aim[idx];
    float inv = 1.0f / (Ar * Ar + Ai * Ai);
    float rre = (Ere * Ar + Eim * Ai) * inv;
    float rim = (Eim * Ar - Ere * Ai) * inv;
    float cr = Cre[idx], ci = Cim[idx];
    g_ctre[idx] = cr * rre - ci * rim;
    g_ctim[idx] = cr * rim + ci * rre;
    g_wre[idx]  = wre;
    g_wim[idx]  = wim;
}

// ---------------- scan pass 1 (f32x2 packed) ---------------------------------------
__global__ __launch_bounds__(256) void scan_part1(const float* __restrict__ x) {
    int tid  = threadIdx.x;
    int gid  = blockIdx.x * 32 + (tid >> 3);
    int lane = tid & 7;
    int seg  = gid % (SEG - 1);
    int rem  = gid / (SEG - 1);
    int h = rem & (HDIM - 1);
    int b = rem >> 9;

    uint64_t wre01[4], wim01[4], nwim01[4], sre01[4], sim01[4];
    int base = h * NST + lane * 8;
#pragma unroll
    for (int p = 0; p < 4; p++) {
        float w0 = g_wre[base + 2*p], w1 = g_wre[base + 2*p + 1];
        float i0 = g_wim[base + 2*p], i1 = g_wim[base + 2*p + 1];
        wre01[p]  = pk2(w0, w1);
        wim01[p]  = pk2(i0, i1);
        nwim01[p] = pk2(-i0, -i1);
        sre01[p] = 0; sim01[p] = 0;
    }
    const float* xp = x + ((size_t)b * LSEQ + seg * SEGT) * HDIM + h;

    float ucur = __ldg(xp + (size_t)lane * HDIM);
    for (int l0 = 0; l0 < SEGT; l0 += 8) {
        int ln = l0 + 8 + lane; if (ln > SEGT - 1) ln = SEGT - 1;
        float unext = __ldg(xp + (size_t)ln * HDIM);
#pragma unroll
        for (int k = 0; k < 8; k++) {
            float u = __shfl_sync(0xffffffffu, ucur, k, 8);
            uint64_t u2 = pk2(u, u);
#pragma unroll
            for (int p = 0; p < 4; p++) {
                uint64_t nr = fma2(wre01[p], sre01[p], fma2(nwim01[p], sim01[p], u2));
                uint64_t ni = fma2(wim01[p], sre01[p], mul2(wre01[p], sim01[p]));
                sre01[p] = nr; sim01[p] = ni;
            }
        }
        ucur = unext;
    }

    size_t ob = (((size_t)(b * HDIM + h) * SEG) + seg) * NST + lane * 8;
#pragma unroll
    for (int p = 0; p < 4; p++) {
        float r0, r1, i0, i1;
        upk2(sre01[p], r0, r1);
        upk2(sim01[p], i0, i1);
        g_sendre[ob + 2*p] = r0; g_sendre[ob + 2*p + 1] = r1;
        g_sendim[ob + 2*p] = i0; g_sendim[ob + 2*p + 1] = i1;
    }
}

// ---------------- combine ----------------------------------------------------------
__global__ __launch_bounds__(256) void scan_combine() {
    int idx = blockIdx.x * blockDim.x + threadIdx.x;
    int n = idx & (NST - 1);
    int rem = idx >> 6;
    int h = rem & (HDIM - 1);
    int b = rem >> 9;
    float wTre = g_wTre[h * NST + n];
    float wTim = g_wTim[h * NST + n];
    float cr = 0.0f, ci = 0.0f;
    size_t base = ((size_t)(b * HDIM + h) * SEG) * NST + n;
#pragma unroll
    for (int j = 0; j < SEG; j++) {
        g_carre[base + (size_t)j * NST] = cr;
        g_carim[base + (size_t)j * NST] = ci;
        if (j < SEG - 1) {
            float er = g_sendre[base + (size_t)j * NST];
            float ei = g_sendim[base + (size_t)j * NST];
            float nr = fmaf(wTre, cr, fmaf(-wTim, ci, er));
            float ni = fmaf(wTim, cr, fmaf(wTre, ci, ei));
            cr = nr; ci = ni;
        }
    }
}

// ---------------- scan pass 2: transpose-reduce over 8-step batches ---------------
__global__ __launch_bounds__(256) void scan_part2(const float* __restrict__ x,
                                                  const float* __restrict__ Dskip,
                                                  bf16* __restrict__ yh,
                                                  bf16* __restrict__ yl) {
    int tid  = threadIdx.x;
    int gid  = blockIdx.x * 32 + (tid >> 3);
    int lane = tid & 7;
    int seg  = gid & (SEG - 1);
    int rem  = gid >> 4;
    int h = rem & (HDIM - 1);
    int b = rem >> 9;

    uint64_t wre01[4], wim01[4], nwim01[4], cre01[4], ncim01[4], sre01[4], sim01[4];
    int base = h * NST + lane * 8;
    size_t cb = (((size_t)(b * HDIM + h) * SEG) + seg) * NST + lane * 8;
#pragma unroll
    for (int p = 0; p < 4; p++) {
        float w0 = g_wre[base + 2*p], w1 = g_wre[base + 2*p + 1];
        float i0 = g_wim[base + 2*p], i1 = g_wim[base + 2*p + 1];
        float c0 = g_ctre[base + 2*p], c1 = g_ctre[base + 2*p + 1];
        float d0 = g_ctim[base + 2*p], d1 = g_ctim[base + 2*p + 1];
        wre01[p]  = pk2(w0, w1);
        wim01[p]  = pk2(i0, i1);
        nwim01[p] = pk2(-i0, -i1);
        cre01[p]  = pk2(c0, c1);
        ncim01[p] = pk2(-d0, -d1);
        sre01[p] = pk2(g_carre[cb + 2*p], g_carre[cb + 2*p + 1]);
        sim01[p] = pk2(g_carim[cb + 2*p], g_carim[cb + 2*p + 1]);
    }
    float Dv = Dskip[h];
    const float* xp = x + ((size_t)b * LSEQ + seg * SEGT) * HDIM + h;
    size_t orow = ((size_t)b * LSEQ + seg * SEGT) * HDIM + h;

    bool l1 = (lane & 1), l2 = (lane & 2), l4 = (lane & 4);

    float ucur = __ldg(xp + (size_t)lane * HDIM);
    for (int l0 = 0; l0 < SEGT; l0 += 8) {
        int ln = l0 + 8 + lane; if (ln > SEGT - 1) ln = SEGT - 1;
        float unext = __ldg(xp + (size_t)ln * HDIM);

        float pbuf[8];
#pragma unroll
        for (int k = 0; k < 8; k++) {
            float u = __shfl_sync(0xffffffffu, ucur, k, 8);
            uint64_t u2 = pk2(u, u);
            uint64_t accR, accI;
            {
                uint64_t nr = fma2(wre01[0], sre01[0], fma2(nwim01[0], sim01[0], u2));
                uint64_t ni = fma2(wim01[0], sre01[0], mul2(wre01[0], sim01[0]));
                sre01[0] = nr; sim01[0] = ni;
                accR = mul2(cre01[0], nr);
                accI = mul2(ncim01[0], ni);
            }
#pragma unroll
            for (int p = 1; p < 4; p++) {
                uint64_t nr = fma2(wre01[p], sre01[p], fma2(nwim01[p], sim01[p], u2));
                uint64_t ni = fma2(wim01[p], sre01[p], mul2(wre01[p], sim01[p]));
                sre01[p] = nr; sim01[p] = ni;
                accR = fma2(cre01[p], nr, accR);
                accI = fma2(ncim01[p], ni, accI);
            }
            uint64_t t = add2(accR, accI);
            float ta, tb; upk2(t, ta, tb);
            pbuf[k] = ta + tb;
        }

        // recursive-halving transpose reduce: lane k ends with sum of pbuf[k]
        float q[4], r[2], sfin;
#pragma unroll
        for (int j = 0; j < 4; j++) {
            float a = pbuf[2*j], bb = pbuf[2*j + 1];
            float sendv = l1 ? a : bb;
            float keepv = l1 ? bb : a;
            q[j] = keepv + __shfl_xor_sync(0xffffffffu, sendv, 1, 8);
        }
#pragma unroll
        for (int j = 0; j < 2; j++) {
            float a = q[2*j], bb = q[2*j + 1];
            float sendv = l2 ? a : bb;
            float keepv = l2 ? bb : a;
            r[j] = keepv + __shfl_xor_sync(0xffffffffu, sendv, 2, 8);
        }
        {
            float sendv = l4 ? r[0] : r[1];
            float keepv = l4 ? r[1] : r[0];
            sfin = keepv + __shfl_xor_sync(0xffffffffu, sendv, 4, 8);
        }

        // lane k outputs step l0+k; its own ucur IS u[l0+k]
        float vv = fmaf(2.0f, sfin, Dv * ucur);
        float c = 0.7978845608028654f * (vv + 0.044715f * vv * vv * vv);
        float gv = vv / (1.0f + __expf(-2.0f * c));
        bf16 hh, ll; split1(gv, hh, ll);
        size_t o = orow + (size_t)(l0 + lane) * HDIM;
        yh[o] = hh;
        yl[o] = ll;

        ucur = unext;
    }
}

// ======================= mma.sync split-bf16 GEMM, cp.async 2-stage, 1 sync/chunk ==
#define LDSB   80
#define TILEB  (128 * LDSB)
#define STAGEB (4 * TILEB)
#define NSTAGE 2
#define GEMM_SMEM (NSTAGE * STAGEB)   // 81920 bytes -> 2 CTAs/SM

__global__ void __launch_bounds__(256, 2)
gemm_mma(const bf16* __restrict__ Ah, const bf16* __restrict__ Al,
         const bf16* __restrict__ Bh, const bf16* __restrict__ Bl,
         const float* __restrict__ bias,
         float* __restrict__ C, bf16* __restrict__ Ch, bf16* __restrict__ Cl,
         int K, int N, int mode) {
    extern __shared__ char smem[];
    uint32_t sbase = smem_u32(smem);
    int tid = threadIdx.x, wid = tid >> 5, lane = tid & 31;
    int row0 = blockIdx.y * 128, col0 = blockIdx.x * 128;
    int wm = wid >> 1, wn = wid & 1;

    float acc[2][8][4];
#pragma unroll
    for (int i = 0; i < 2; i++)
#pragma unroll
        for (int j = 0; j < 8; j++)
#pragma unroll
            for (int q = 0; q < 4; q++) acc[i][j][q] = 0.0f;

    int lr = tid >> 1;
    int lc = (tid & 1) * 16;
    const bf16* aph = Ah + (size_t)(row0 + lr) * K + lc;
    const bf16* apl = Al + (size_t)(row0 + lr) * K + lc;
    const bf16* bph = Bh + (size_t)(col0 + lr) * K + lc;
    const bf16* bpl = Bl + (size_t)(col0 + lr) * K + lc;
    uint32_t soff = (uint32_t)(lr * LDSB + lc * 2);

    int nch = K / 32;

    auto issue = [&](int c, int s) {
        uint32_t st = sbase + (uint32_t)s * STAGEB;
        int go = c * 32;
        uint32_t ah = st + soff;
        CP_ASYNC16(ah,              aph + go);
        CP_ASYNC16(ah + 16,         aph + go + 8);
        CP_ASYNC16(ah + TILEB,      apl + go);
        CP_ASYNC16(ah + TILEB + 16, apl + go + 8);
        uint32_t bh = st + 2 * TILEB + soff;
        CP_ASYNC16(bh,              bph + go);
        CP_ASYNC16(bh + 16,         bph + go + 8);
        CP_ASYNC16(bh + TILEB,      bpl + go);
        CP_ASYNC16(bh + TILEB + 16, bpl + go + 8);
    };

    // prologue: chunk 0 into stage 0
    issue(0, 0);
    CP_COMMIT();

    int r_lm = (lane & 7) + ((lane >> 3) & 1) * 8;
    int k_lm = ((lane >> 4) & 1) * 8;

    for (int c = 0; c < nch; ++c) {
        CP_WAIT(0);               // chunk c complete
        __syncthreads();          // all warps done with chunk c-1's stage
        if (c + 1 < nch) {        // load c+1 into the freed stage, overlaps compute
            issue(c + 1, (c + 1) & 1);
            CP_COMMIT();
        }

        uint32_t st = sbase + (uint32_t)(c & 1) * STAGEB;
        uint32_t ahs = st;
        uint32_t bhs = st + 2 * TILEB;

#pragma unroll
        for (int ks = 0; ks < 2; ++ks) {
            int kcol = ks * 16 + k_lm;
            uint32_t afh[2][4], afl[2][4];
#pragma unroll
            for (int mi = 0; mi < 2; ++mi) {
                int m = wm * 32 + mi * 16 + r_lm;
                uint32_t ad = ahs + (uint32_t)(m * LDSB + kcol * 2);
                ldmatrix_x4(afh[mi], ad);
                ldmatrix_x4(afl[mi], ad + TILEB);
            }
#pragma unroll
            for (int nj = 0; nj < 4; ++nj) {
                uint32_t bfh[4], bfl[4];
                int n = wn * 64 + nj * 16 + r_lm;
                uint32_t bd = bhs + (uint32_t)(n * LDSB + kcol * 2);
                ldmatrix_x4(bfh, bd);
                ldmatrix_x4(bfl, bd + TILEB);
#pragma unroll
                for (int mi = 0; mi < 2; ++mi)
#pragma unroll
                    for (int h = 0; h < 2; ++h) {
                        float* cc = acc[mi][nj * 2 + h];
                        mma_bf16(cc, afh[mi], bfh[h], bfh[2 + h]);
                        mma_bf16(cc, afh[mi], bfl[h], bfl[2 + h]);
                        mma_bf16(cc, afl[mi], bfh[h], bfh[2 + h]);
                    }
            }
        }
    }

    int tg = lane >> 2, tq = lane & 3;
#pragma unroll
    for (int mi = 0; mi < 2; ++mi) {
        int r = row0 + wm * 32 + mi * 16 + tg;
#pragma unroll
        for (int ni = 0; ni < 8; ++ni) {
            int cix = col0 + wn * 64 + ni * 8 + tq * 2;
            float b0 = bias[cix], b1 = bias[cix + 1];
            float v0 = acc[mi][ni][0] + b0, v1 = acc[mi][ni][1] + b1;
            float v2 = acc[mi][ni][2] + b0, v3 = acc[mi][ni][3] + b1;
            if (mode == 0) {
                *(float2*)(C + (size_t)r * N + cix) = make_float2(v0, v1);
                *(float2*)(C + (size_t)(r + 8) * N + cix) = make_float2(v2, v3);
            } else {
                v0 = fmaxf(v0, 0.0f); v1 = fmaxf(v1, 0.0f);
                v2 = fmaxf(v2, 0.0f); v3 = fmaxf(v3, 0.0f);
                bf16 h0, l0, h1, l1;
                split1(v0, h0, l0); split1(v1, h1, l1);
                *(bf162*)(Ch + (size_t)r * N + cix) = bf162(h0, h1);
                *(bf162*)(Cl + (size_t)r * N + cix) = bf162(l0, l1);
                split1(v2, h0, l0); split1(v3, h1, l1);
                *(bf162*)(Ch + (size_t)(r + 8) * N + cix) = bf162(h0, h1);
                *(bf162*)(Cl + (size_t)(r + 8) * N + cix) = bf162(l0, l1);
            }
        }
    }
}

// ---------------- block reduce helper ---------------------------------------------
__device__ __forceinline__ float2 block_reduce_2(float a, float b) {
    unsigned m = 0xffffffffu;
#pragma unroll
    for (int o = 16; o > 0; o >>= 1) {
        a += __shfl_down_sync(m, a, o);
        b += __shfl_down_sync(m, b, o);
    }
    __shared__ float sa[4], sb[4];
    int w = threadIdx.x >> 5, lane = threadIdx.x & 31;
    if (lane == 0) { sa[w] = a; sb[w] = b; }
    __syncthreads();
    if (threadIdx.x == 0) {
        float ta = sa[0] + sa[1] + sa[2] + sa[3];
        float tb = sb[0] + sb[1] + sb[2] + sb[3];
        sa[0] = ta; sb[0] = tb;
    }
    __syncthreads();
    return make_float2(sa[0], sb[0]);
}

// ---------------- GLU + residual + LN1 ---------------------------------------------
__global__ __launch_bounds__(128) void glu_ln_kernel(const float* __restrict__ z,
                                                     const float* __restrict__ x,
                                                     const float* __restrict__ g1,
                                                     const float* __restrict__ b1,
                                                     float* __restrict__ xln,
                                                     bf16* __restrict__ xh,
                                                     bf16* __restrict__ xl) {
    int row = blockIdx.x, tid = threadIdx.x;
    const float* zr = z + (size_t)row * (2 * HDIM);
    const float* xr = x + (size_t)row * HDIM;
    float v[4], s = 0.0f, s2 = 0.0f;
#pragma unroll
    for (int i = 0; i < 4; i++) {
        int c = tid + i * 128;
        float a = zr[c], g = zr[c + HDIM];
        float val = xr[c] + a / (1.0f + __expf(-g));
        v[i] = val; s += val; s2 += val * val;
    }
    float2 tot = block_reduce_2(s, s2);
    float mu = tot.x * (1.0f / HDIM);
    float var = tot.y * (1.0f / HDIM) - mu * mu;
    float rstd = rsqrtf(var + 1e-5f);
#pragma unroll
    for (int i = 0; i < 4; i++) {
        int c = tid + i * 128;
        float o = (v[i] - mu) * rstd * g1[c] + b1[c];
        xln[(size_t)row * HDIM + c] = o;
        bf16 hh, ll; split1(o, hh, ll);
        xh[(size_t)row * HDIM + c] = hh;
        xl[(size_t)row * HDIM + c] = ll;
    }
}

// ---------------- residual + LN2 ---------------------------------------------------
__global__ __launch_bounds__(128) void final_ln_kernel(const float* __restrict__ xln,
                                                       const float* __restrict__ y2,
                                                       const float* __restrict__ g2,
                                                       const float* __restrict__ b2,
                                                       float* __restrict__ out) {
    int row = blockIdx.x, tid = threadIdx.x;
    const float* a = xln + (size_t)row * HDIM;
    const float* b = y2 + (size_t)row * HDIM;
    float v[4], s = 0.0f, s2 = 0.0f;
#pragma unroll
    for (int i = 0; i < 4; i++) {
        int c = tid + i * 128;
        float val = a[c] + b[c];
        v[i] = val; s += val; s2 += val * val;
    }
    float2 tot = block_reduce_2(s, s2);
    float mu = tot.x * (1.0f / HDIM);
    float var = tot.y * (1.0f / HDIM) - mu * mu;
    float rstd = rsqrtf(var + 1e-5f);
#pragma unroll
    for (int i = 0; i < 4; i++) {
        int c = tid + i * 128;
        out[(size_t)row * HDIM + c] = (v[i] - mu) * rstd * g2[c] + b2[c];
    }
}

// ---------------- launch ------------------------------------------------------------
extern "C" void kernel_launch(void* const* d_in, const int* in_sizes, int n_in,
                              void* d_out, int out_size) {
    const float* x      = (const float*)d_in[0];
    const float* log_dt = (const float*)d_in[1];
    const float* A_re   = (const float*)d_in[2];
    const float* A_im   = (const float*)d_in[3];
    const float* C_re   = (const float*)d_in[4];
    const float* C_im   = (const float*)d_in[5];
    const float* D_skip = (const float*)d_in[6];
    const float* W_out  = (const float*)d_in[7];
    const float* b_out  = (const float*)d_in[8];
    const float* g1     = (const float*)d_in[9];
    const float* beta1  = (const float*)d_in[10];
    const float* g2     = (const float*)d_in[11];
    const float* beta2  = (const float*)d_in[12];
    const float* W1     = (const float*)d_in[13];
    const float* bc1    = (const float*)d_in[14];
    const float* W2     = (const float*)d_in[15];
    const float* bc2    = (const float*)d_in[16];
    float* out = (float*)d_out;

    bf16 *yh, *yl, *xh, *xl, *y1h, *y1l;
    bf16 *wouth, *woutl, *w1h, *w1l, *w2h, *w2l;
    float *z, *xln, *y2;
    cudaGetSymbolAddress((void**)&yh,  g_yh);
    cudaGetSymbolAddress((void**)&yl,  g_yl);
    cudaGetSymbolAddress((void**)&z,   g_z);
    cudaGetSymbolAddress((void**)&xln, g_xln);
    cudaGetSymbolAddress((void**)&xh,  g_xh);
    cudaGetSymbolAddress((void**)&xl,  g_xl);
    cudaGetSymbolAddress((void**)&y1h, g_y1h);
    cudaGetSymbolAddress((void**)&y1l, g_y1l);
    cudaGetSymbolAddress((void**)&y2,  g_y2);
    cudaGetSymbolAddress((void**)&wouth, g_wouth);
    cudaGetSymbolAddress((void**)&woutl, g_woutl);
    cudaGetSymbolAddress((void**)&w1h, g_w1h);
    cudaGetSymbolAddress((void**)&w1l, g_w1l);
    cudaGetSymbolAddress((void**)&w2h, g_w2h);
    cudaGetSymbolAddress((void**)&w2l, g_w2l);

    cudaFuncSetAttribute(gemm_mma, cudaFuncAttributeMaxDynamicSharedMemorySize, GEMM_SMEM);

    precompute_kernel<<<HDIM, NST>>>(log_dt, A_re, A_im, C_re, C_im);

    scan_part1<<<(BSZ * HDIM * (SEG - 1)) / 32, 256>>>(x);
    scan_combine<<<(BSZ * HDIM * NST) / 256, 256>>>();
    scan_part2<<<(BSZ * HDIM * SEG) / 32, 256>>>(x, D_skip, yh, yl);

    split_all_kernel<<<(4 * HDIM * HDIM + 255) / 256, 256>>>(W_out, W1, W2);

    gemm_mma<<<dim3((2 * HDIM) / 128, ROWS / 128), 256, GEMM_SMEM>>>(
        yh, yl, wouth, woutl, b_out, z, nullptr, nullptr, HDIM, 2 * HDIM, 0);

    glu_ln_kernel<<<ROWS, 128>>>(z, x, g1, beta1, xln, xh, xl);

    gemm_mma<<<dim3(HDIM / 128, ROWS / 128), 256, GEMM_SMEM>>>(
        xh, xl, w1h, w1l, bc1, nullptr, y1h, y1l, HDIM, HDIM, 1);

    gemm_mma<<<dim3(HDIM / 128, ROWS / 128), 256, GEMM_SMEM>>>(
        y1h, y1l, w2h, w2l, bc2, y2, nullptr, nullptr, HDIM, HDIM, 0);

    final_ln_kernel<<<ROWS, 128>>>(xln, y2, g2, beta2, out);
}